// round 10
// baseline (speedup 1.0000x reference)
#include <cuda_runtime.h>
#include <cuda_fp16.h>

#define N_NODES 50000
#define N_EDGES 1600000
#define BKT 128  // fixed bucket capacity per dst (deg ~ Poisson(32); P(>128) ~ 1e-40)

// ---- scratch (static __device__, no allocs) ----
// g_cnt starts zeroed (module load) and is re-zeroed by k_agg7 each run.
__device__ int g_cnt[N_NODES];
__device__ __align__(16) unsigned short g_bucket[N_NODES * BKT];
__device__ __half g_hA[N_NODES * 64];    // pre-agg features, fp16
__device__ float g_bufB[N_NODES * 64];   // post-agg features, fp32
__device__ __half g_h3h[N_NODES * 8];    // layer-3 pre-agg, fp16 (7 used + pad)
__device__ float g_wt1[64 * 64];
__device__ float g_wt2[64 * 64];
__device__ float g_wt3[64 * 8];          // [k*8+j]

// -------- weight transposes (Wt[k][j] = W[j][k]) --------

__global__ void k_prep_w(const float* __restrict__ W1, const float* __restrict__ W2,
                         const float* __restrict__ W3) {
    int t = blockIdx.x * blockDim.x + threadIdx.x;
    if (t < 4096) {
        int j = t >> 6, k = t & 63;
        g_wt1[k * 64 + j] = W1[t];
        g_wt2[k * 64 + j] = W2[t];
    }
    if (t < 512) {
        int k = t >> 3, j = t & 7;
        g_wt3[t] = (j < 7) ? W3[j * 64 + k] : 0.f;
    }
}

// ------ direct bucket scatter: no hist, no scan; 8 edges/thread ------

__global__ void k_scatter(const int* __restrict__ ei) {
    int i = (blockIdx.x * blockDim.x + threadIdx.x) * 8;
    if (i < N_EDGES) {
        int4 sA = *(const int4*)&ei[i];
        int4 sB = *(const int4*)&ei[i + 4];
        int4 dA = *(const int4*)&ei[N_EDGES + i];
        int4 dB = *(const int4*)&ei[N_EDGES + i + 4];
        int p0 = ((unsigned)dA.x < N_NODES) ? atomicAdd(&g_cnt[dA.x], 1) : -1;
        int p1 = ((unsigned)dA.y < N_NODES) ? atomicAdd(&g_cnt[dA.y], 1) : -1;
        int p2 = ((unsigned)dA.z < N_NODES) ? atomicAdd(&g_cnt[dA.z], 1) : -1;
        int p3 = ((unsigned)dA.w < N_NODES) ? atomicAdd(&g_cnt[dA.w], 1) : -1;
        int p4 = ((unsigned)dB.x < N_NODES) ? atomicAdd(&g_cnt[dB.x], 1) : -1;
        int p5 = ((unsigned)dB.y < N_NODES) ? atomicAdd(&g_cnt[dB.y], 1) : -1;
        int p6 = ((unsigned)dB.z < N_NODES) ? atomicAdd(&g_cnt[dB.z], 1) : -1;
        int p7 = ((unsigned)dB.w < N_NODES) ? atomicAdd(&g_cnt[dB.w], 1) : -1;
        if ((unsigned)p0 < BKT) g_bucket[dA.x * BKT + p0] = (unsigned short)sA.x;
        if ((unsigned)p1 < BKT) g_bucket[dA.y * BKT + p1] = (unsigned short)sA.y;
        if ((unsigned)p2 < BKT) g_bucket[dA.z * BKT + p2] = (unsigned short)sA.z;
        if ((unsigned)p3 < BKT) g_bucket[dA.w * BKT + p3] = (unsigned short)sA.w;
        if ((unsigned)p4 < BKT) g_bucket[dB.x * BKT + p4] = (unsigned short)sB.x;
        if ((unsigned)p5 < BKT) g_bucket[dB.y * BKT + p5] = (unsigned short)sB.y;
        if ((unsigned)p6 < BKT) g_bucket[dB.z * BKT + p6] = (unsigned short)sB.z;
        if ((unsigned)p7 < BKT) g_bucket[dB.w * BKT + p7] = (unsigned short)sB.w;
    }
}

// ---- packed f32x2 helpers (Blackwell FFMA2) ----

__device__ __forceinline__ unsigned long long pack2(float lo, float hi) {
    unsigned long long p;
    asm("mov.b64 %0, {%1, %2};" : "=l"(p) : "f"(lo), "f"(hi));
    return p;
}
__device__ __forceinline__ void unpack2(unsigned long long p, float& lo, float& hi) {
    asm("mov.b64 {%0, %1}, %2;" : "=f"(lo), "=f"(hi) : "l"(p));
}
__device__ __forceinline__ void ffma2(unsigned long long& d, unsigned long long a,
                                      unsigned long long b) {
    asm("fma.rn.f32x2 %0, %1, %2, %0;" : "+l"(d) : "l"(a), "l"(b));
}

// ------- GEMM 64x64 fp32-in -> fp16 out, f32x2 packed FMA -------

__global__ __launch_bounds__(256) void k_gemm64h(const float* __restrict__ in,
                                                 const float* __restrict__ wt,
                                                 __half* __restrict__ out) {
    __shared__ __align__(16) float sW[64 * 64];
    __shared__ float sX[64 * 65];
    int n0 = blockIdx.x * 64;
    for (int i = threadIdx.x; i < 4096; i += 256) sW[i] = wt[i];
    for (int i = threadIdx.x; i < 4096; i += 256) {
        int n = i >> 6, k = i & 63;
        sX[n * 65 + k] = (n0 + n < N_NODES) ? in[(n0 + n) * 64 + k] : 0.f;
    }
    __syncthreads();
    int tx = threadIdx.x & 15, ty = threadIdx.x >> 4;
    unsigned long long accP[4][2] = {};
    #pragma unroll 8
    for (int k = 0; k < 64; k++) {
        double2 wd = *(const double2*)&sW[k * 64 + tx * 4];
        unsigned long long w01 = __double_as_longlong(wd.x);
        unsigned long long w23 = __double_as_longlong(wd.y);
        #pragma unroll
        for (int i = 0; i < 4; i++) {
            float xv = sX[(ty * 4 + i) * 65 + k];
            unsigned long long xp = pack2(xv, xv);
            ffma2(accP[i][0], xp, w01);
            ffma2(accP[i][1], xp, w23);
        }
    }
    #pragma unroll
    for (int i = 0; i < 4; i++) {
        int n = n0 + ty * 4 + i;
        if (n < N_NODES) {
            float a0, a1, a2, a3;
            unpack2(accP[i][0], a0, a1);
            unpack2(accP[i][1], a2, a3);
            __half2 h0 = __floats2half2_rn(a0, a1);
            __half2 h1 = __floats2half2_rn(a2, a3);
            uint2 pk = {*(unsigned*)&h0, *(unsigned*)&h1};
            *(uint2*)&out[n * 64 + tx * 4] = pk;
        }
    }
}

// ---- aggregation 64ch: warp/node, 16 lanes x 4ch, 2 edge slots ----
// HADD2 pairwise tree over 4 edges before cvt -> fp32 accumulate.
// PROJ=false: +bias,relu -> fp32 out.  PROJ=true: +bias,relu -> @W3 -> fp16 g_h3h.

template <bool PROJ>
__global__ __launch_bounds__(256) void k_agg64v(const uint2* __restrict__ f2,
                                                const float* __restrict__ bias,
                                                float* __restrict__ out) {
    __shared__ float sW3T[512];  // transposed W3: [j*64 + k]
    if (PROJ) {
        for (int i = threadIdx.x; i < 512; i += 256) {
            int j = i >> 6, k = i & 63;
            sW3T[i] = g_wt3[k * 8 + j];
        }
        __syncthreads();
    }
    int n = (blockIdx.x * blockDim.x + threadIdx.x) >> 5;
    int lane = threadIdx.x & 31;
    if (n >= N_NODES) return;
    int cl = lane & 15;            // channel group: 4 ch = [cl*4, cl*4+4)
    int eslot = lane >> 4;         // which edge of each pair
    int sh = eslot << 4;
    int cnt = min(g_cnt[n], BKT);
    const unsigned short* __restrict__ row = g_bucket + n * BKT;
    const uint4* __restrict__ idx4 = (const uint4*)row;
    float a0 = 0.f, a1 = 0.f, a2 = 0.f, a3 = 0.f;
    int e = 0;
    for (; e + 8 <= cnt; e += 8) {   // this slot handles 4 of the 8 edges
        uint4 q = idx4[e >> 3];
        int s0 = (q.x >> sh) & 0xFFFF;
        int s1 = (q.y >> sh) & 0xFFFF;
        int s2 = (q.z >> sh) & 0xFFFF;
        int s3 = (q.w >> sh) & 0xFFFF;
        uint2 u0 = f2[s0 * 16 + cl];
        uint2 u1 = f2[s1 * 16 + cl];
        uint2 u2 = f2[s2 * 16 + cl];
        uint2 u3 = f2[s3 * 16 + cl];
        // fp16 pairwise tree (2 roundings) then one fp32 accumulate
        __half2 lo = __hadd2(__hadd2(*(__half2*)&u0.x, *(__half2*)&u1.x),
                             __hadd2(*(__half2*)&u2.x, *(__half2*)&u3.x));
        __half2 hi = __hadd2(__hadd2(*(__half2*)&u0.y, *(__half2*)&u1.y),
                             __hadd2(*(__half2*)&u2.y, *(__half2*)&u3.y));
        float2 plo = __half22float2(lo);
        float2 phi = __half22float2(hi);
        a0 += plo.x; a1 += plo.y; a2 += phi.x; a3 += phi.y;
    }
    for (; e < cnt; e += 2) {      // tail: warp-uniform bound, per-slot guard
        if (e + eslot < cnt) {
            int s = row[e + eslot];
            uint2 u = f2[s * 16 + cl];
            float2 p;
            p = __half22float2(*(__half2*)&u.x); a0 += p.x; a1 += p.y;
            p = __half22float2(*(__half2*)&u.y); a2 += p.x; a3 += p.y;
        }
    }
    // combine the two edge-slot halves
    a0 += __shfl_xor_sync(~0u, a0, 16);
    a1 += __shfl_xor_sync(~0u, a1, 16);
    a2 += __shfl_xor_sync(~0u, a2, 16);
    a3 += __shfl_xor_sync(~0u, a3, 16);
    float4 b = ((const float4*)bias)[cl];
    a0 = fmaxf(a0 + b.x, 0.f);
    a1 = fmaxf(a1 + b.y, 0.f);
    a2 = fmaxf(a2 + b.z, 0.f);
    a3 = fmaxf(a3 + b.w, 0.f);
    if (!PROJ) {
        if (eslot == 0)
            ((float4*)out)[n * 16 + cl] = make_float4(a0, a1, a2, a3);
    } else {
        // project 64 -> 7 (bias b3 added post-aggregation in k_agg7)
        float pj[7];
        int k0 = cl * 4;
        #pragma unroll
        for (int j = 0; j < 7; j++) {
            const float* wj = &sW3T[j * 64 + k0];
            pj[j] = a0 * wj[0] + a1 * wj[1] + a2 * wj[2] + a3 * wj[3];
        }
        #pragma unroll
        for (int o = 8; o; o >>= 1)
            #pragma unroll
            for (int j = 0; j < 7; j++)
                pj[j] += __shfl_xor_sync(~0u, pj[j], o, 16);
        if (lane == 0) {
            __half2 h0 = __floats2half2_rn(pj[0], pj[1]);
            __half2 h1 = __floats2half2_rn(pj[2], pj[3]);
            __half2 h2v = __floats2half2_rn(pj[4], pj[5]);
            __half2 h3v = __floats2half2_rn(pj[6], 0.f);
            uint4 pk = {*(unsigned*)&h0, *(unsigned*)&h1,
                        *(unsigned*)&h2v, *(unsigned*)&h3v};
            *(uint4*)&g_h3h[n * 8] = pk;
        }
    }
}

// ---- aggregation 7ch + bias + log_softmax, thread per node; zeroes g_cnt ----

__global__ __launch_bounds__(256) void k_agg7(const float* __restrict__ b3,
                                              float* __restrict__ out) {
    int n = blockIdx.x * blockDim.x + threadIdx.x;
    if (n >= N_NODES) return;
    int cnt = min(g_cnt[n], BKT);
    g_cnt[n] = 0;  // self-clean for next replay (last consumer of g_cnt)
    const unsigned short* __restrict__ row = g_bucket + n * BKT;
    const uint4* __restrict__ p = (const uint4*)g_h3h;
    float a[7] = {};
    int e = 0;
    for (; e + 2 <= cnt; e += 2) {
        int s0 = row[e], s1 = row[e + 1];
        uint4 q0 = p[s0];
        uint4 q1 = p[s1];
        __half2 h0 = __hadd2(*(__half2*)&q0.x, *(__half2*)&q1.x);
        __half2 h1 = __hadd2(*(__half2*)&q0.y, *(__half2*)&q1.y);
        __half2 h2v = __hadd2(*(__half2*)&q0.z, *(__half2*)&q1.z);
        __half2 h3v = __hadd2(*(__half2*)&q0.w, *(__half2*)&q1.w);
        float2 f0 = __half22float2(h0);
        float2 f1 = __half22float2(h1);
        float2 f2v = __half22float2(h2v);
        float2 f3 = __half22float2(h3v);
        a[0] += f0.x; a[1] += f0.y; a[2] += f1.x; a[3] += f1.y;
        a[4] += f2v.x; a[5] += f2v.y; a[6] += f3.x;
    }
    for (; e < cnt; e++) {
        uint4 q = p[row[e]];
        float2 f0 = __half22float2(*(__half2*)&q.x);
        float2 f1 = __half22float2(*(__half2*)&q.y);
        float2 f2v = __half22float2(*(__half2*)&q.z);
        float2 f3 = __half22float2(*(__half2*)&q.w);
        a[0] += f0.x; a[1] += f0.y; a[2] += f1.x; a[3] += f1.y;
        a[4] += f2v.x; a[5] += f2v.y; a[6] += f3.x;
    }
    #pragma unroll
    for (int j = 0; j < 7; j++) a[j] += b3[j];
    float m = a[0];
    #pragma unroll
    for (int j = 1; j < 7; j++) m = fmaxf(m, a[j]);
    float se = 0.f;
    #pragma unroll
    for (int j = 0; j < 7; j++) se += __expf(a[j] - m);
    float ls = __logf(se);
    #pragma unroll
    for (int j = 0; j < 7; j++) out[n * 7 + j] = a[j] - m - ls;
}

// -------- launch: scatter at t=0 on main; prep+gemm1 on side stream --------

static cudaStream_t g_s2 = nullptr;
static cudaEvent_t g_evF = nullptr, g_evJ = nullptr;

extern "C" void kernel_launch(void* const* d_in, const int* in_sizes, int n_in,
                              void* d_out, int out_size) {
    const float* x = (const float*)d_in[0];
    const int* ei = (const int*)d_in[1];
    const float* W1 = (const float*)d_in[2];
    const float* b1 = (const float*)d_in[3];
    const float* W2 = (const float*)d_in[4];
    const float* b2 = (const float*)d_in[5];
    const float* W3 = (const float*)d_in[6];
    const float* b3 = (const float*)d_in[7];
    float* out = (float*)d_out;

    if (!g_s2) {
        cudaStreamCreateWithFlags(&g_s2, cudaStreamNonBlocking);
        cudaEventCreateWithFlags(&g_evF, cudaEventDisableTiming);
        cudaEventCreateWithFlags(&g_evJ, cudaEventDisableTiming);
    }

    void *pA, *pB, *pw1, *pw2;
    cudaGetSymbolAddress(&pA, g_hA);
    cudaGetSymbolAddress(&pB, g_bufB);
    cudaGetSymbolAddress(&pw1, g_wt1);
    cudaGetSymbolAddress(&pw2, g_wt2);

    // fork: side stream does weight prep + layer-1 GEMM
    cudaEventRecord(g_evF, 0);
    cudaStreamWaitEvent(g_s2, g_evF, 0);
    k_prep_w<<<16, 256, 0, g_s2>>>(W1, W2, W3);
    k_gemm64h<<<(N_NODES + 63) / 64, 256, 0, g_s2>>>(x, (const float*)pw1, (__half*)pA);
    cudaEventRecord(g_evJ, g_s2);

    // main stream: bucket scatter starts immediately (g_cnt pre-zeroed)
    k_scatter<<<(N_EDGES / 8 + 255) / 256, 256>>>(ei);

    // join
    cudaStreamWaitEvent(0, g_evJ, 0);

    // layer 2
    k_agg64v<false><<<(N_NODES * 32 + 255) / 256, 256>>>((const uint2*)pA, b1, (float*)pB);
    k_gemm64h<<<(N_NODES + 63) / 64, 256>>>((const float*)pB, (const float*)pw2, (__half*)pA);
    // layer 3: agg + fused projection, then final agg + log_softmax (+cnt reset)
    k_agg64v<true><<<(N_NODES * 32 + 255) / 256, 256>>>((const uint2*)pA, b2, nullptr);
    k_agg7<<<(N_NODES + 255) / 256, 256>>>(b3, out);
}

// round 11
// speedup vs baseline: 1.1105x; 1.1105x over previous
#include <cuda_runtime.h>
#include <cuda_fp16.h>

#define N_NODES 50000
#define N_EDGES 1600000
#define BKT 128  // fixed bucket capacity per dst (deg ~ Poisson(32); P(>128) ~ 1e-40)

// ---- scratch (static __device__, no allocs) ----
__device__ int g_cnt[N_NODES];
__device__ __align__(16) unsigned short g_bucket[N_NODES * BKT];
__device__ __half g_hA[N_NODES * 64];    // pre-agg features, fp16
__device__ float g_bufB[N_NODES * 64];   // post-agg features, fp32
__device__ __half g_h3h[N_NODES * 8];    // layer-3 pre-agg, fp16 (7 used + pad)
__device__ float g_wt1[64 * 64];
__device__ float g_wt2[64 * 64];
__device__ float g_wt3[64 * 8];          // [k*8+j]

// ------ zero counters + weight transposes, one index-dispatched kernel ------

__global__ void k_zero_prep(const float* __restrict__ W1, const float* __restrict__ W2,
                            const float* __restrict__ W3) {
    int i = blockIdx.x * blockDim.x + threadIdx.x;
    if (i < N_NODES) { g_cnt[i] = 0; return; }
    int t = i - N_NODES;
    if (t < 4096) { int j = t >> 6, k = t & 63; g_wt1[k * 64 + j] = W1[t]; return; }
    t -= 4096;
    if (t < 4096) { int j = t >> 6, k = t & 63; g_wt2[k * 64 + j] = W2[t]; return; }
    t -= 4096;
    if (t < 512) { int k = t >> 3, j = t & 7; g_wt3[t] = (j < 7) ? W3[j * 64 + k] : 0.f; }
}

// ------ direct bucket scatter: no hist, no scan; 8 edges/thread ------

__global__ void k_scatter(const int* __restrict__ ei) {
    int i = (blockIdx.x * blockDim.x + threadIdx.x) * 8;
    if (i < N_EDGES) {
        int4 sA = *(const int4*)&ei[i];
        int4 sB = *(const int4*)&ei[i + 4];
        int4 dA = *(const int4*)&ei[N_EDGES + i];
        int4 dB = *(const int4*)&ei[N_EDGES + i + 4];
        int p0 = ((unsigned)dA.x < N_NODES) ? atomicAdd(&g_cnt[dA.x], 1) : -1;
        int p1 = ((unsigned)dA.y < N_NODES) ? atomicAdd(&g_cnt[dA.y], 1) : -1;
        int p2 = ((unsigned)dA.z < N_NODES) ? atomicAdd(&g_cnt[dA.z], 1) : -1;
        int p3 = ((unsigned)dA.w < N_NODES) ? atomicAdd(&g_cnt[dA.w], 1) : -1;
        int p4 = ((unsigned)dB.x < N_NODES) ? atomicAdd(&g_cnt[dB.x], 1) : -1;
        int p5 = ((unsigned)dB.y < N_NODES) ? atomicAdd(&g_cnt[dB.y], 1) : -1;
        int p6 = ((unsigned)dB.z < N_NODES) ? atomicAdd(&g_cnt[dB.z], 1) : -1;
        int p7 = ((unsigned)dB.w < N_NODES) ? atomicAdd(&g_cnt[dB.w], 1) : -1;
        if ((unsigned)p0 < BKT) g_bucket[dA.x * BKT + p0] = (unsigned short)sA.x;
        if ((unsigned)p1 < BKT) g_bucket[dA.y * BKT + p1] = (unsigned short)sA.y;
        if ((unsigned)p2 < BKT) g_bucket[dA.z * BKT + p2] = (unsigned short)sA.z;
        if ((unsigned)p3 < BKT) g_bucket[dA.w * BKT + p3] = (unsigned short)sA.w;
        if ((unsigned)p4 < BKT) g_bucket[dB.x * BKT + p4] = (unsigned short)sB.x;
        if ((unsigned)p5 < BKT) g_bucket[dB.y * BKT + p5] = (unsigned short)sB.y;
        if ((unsigned)p6 < BKT) g_bucket[dB.z * BKT + p6] = (unsigned short)sB.z;
        if ((unsigned)p7 < BKT) g_bucket[dB.w * BKT + p7] = (unsigned short)sB.w;
    }
}

// ---- packed f32x2 helpers (Blackwell FFMA2) ----

__device__ __forceinline__ unsigned long long pack2(float lo, float hi) {
    unsigned long long p;
    asm("mov.b64 %0, {%1, %2};" : "=l"(p) : "f"(lo), "f"(hi));
    return p;
}
__device__ __forceinline__ void unpack2(unsigned long long p, float& lo, float& hi) {
    asm("mov.b64 {%0, %1}, %2;" : "=f"(lo), "=f"(hi) : "l"(p));
}
__device__ __forceinline__ void ffma2(unsigned long long& d, unsigned long long a,
                                      unsigned long long b) {
    asm("fma.rn.f32x2 %0, %1, %2, %0;" : "+l"(d) : "l"(a), "l"(b));
}

// ------- GEMM 64x64 fp32-in -> fp16 out, f32x2 packed FMA -------

__global__ __launch_bounds__(256) void k_gemm64h(const float* __restrict__ in,
                                                 const float* __restrict__ wt,
                                                 __half* __restrict__ out) {
    __shared__ __align__(16) float sW[64 * 64];
    __shared__ float sX[64 * 65];
    int n0 = blockIdx.x * 64;
    for (int i = threadIdx.x; i < 4096; i += 256) sW[i] = wt[i];
    for (int i = threadIdx.x; i < 4096; i += 256) {
        int n = i >> 6, k = i & 63;
        sX[n * 65 + k] = (n0 + n < N_NODES) ? in[(n0 + n) * 64 + k] : 0.f;
    }
    __syncthreads();
    int tx = threadIdx.x & 15, ty = threadIdx.x >> 4;
    unsigned long long accP[4][2] = {};
    #pragma unroll 8
    for (int k = 0; k < 64; k++) {
        double2 wd = *(const double2*)&sW[k * 64 + tx * 4];
        unsigned long long w01 = __double_as_longlong(wd.x);
        unsigned long long w23 = __double_as_longlong(wd.y);
        #pragma unroll
        for (int i = 0; i < 4; i++) {
            float xv = sX[(ty * 4 + i) * 65 + k];
            unsigned long long xp = pack2(xv, xv);
            ffma2(accP[i][0], xp, w01);
            ffma2(accP[i][1], xp, w23);
        }
    }
    #pragma unroll
    for (int i = 0; i < 4; i++) {
        int n = n0 + ty * 4 + i;
        if (n < N_NODES) {
            float a0, a1, a2, a3;
            unpack2(accP[i][0], a0, a1);
            unpack2(accP[i][1], a2, a3);
            __half2 h0 = __floats2half2_rn(a0, a1);
            __half2 h1 = __floats2half2_rn(a2, a3);
            uint2 pk = {*(unsigned*)&h0, *(unsigned*)&h1};
            *(uint2*)&out[n * 64 + tx * 4] = pk;
        }
    }
}

// ---- aggregation 64ch: warp/node, 16 lanes x 4ch, 2 edge slots ----
// HADD2 pairwise tree over 4 edges before cvt -> fp32 accumulate.
// PROJ=false: +bias,relu -> fp32 out.  PROJ=true: +bias,relu -> @W3 -> fp16 g_h3h.

template <bool PROJ>
__global__ __launch_bounds__(256) void k_agg64v(const uint2* __restrict__ f2,
                                                const float* __restrict__ bias,
                                                float* __restrict__ out) {
    __shared__ float sW3T[512];  // transposed W3: [j*64 + k]
    if (PROJ) {
        for (int i = threadIdx.x; i < 512; i += 256) {
            int j = i >> 6, k = i & 63;
            sW3T[i] = g_wt3[k * 8 + j];
        }
        __syncthreads();
    }
    int n = (blockIdx.x * blockDim.x + threadIdx.x) >> 5;
    int lane = threadIdx.x & 31;
    if (n >= N_NODES) return;
    int cl = lane & 15;            // channel group: 4 ch = [cl*4, cl*4+4)
    int eslot = lane >> 4;         // which edge of each pair
    int sh = eslot << 4;
    int cnt = min(g_cnt[n], BKT);
    const unsigned short* __restrict__ row = g_bucket + n * BKT;
    const uint4* __restrict__ idx4 = (const uint4*)row;
    float a0 = 0.f, a1 = 0.f, a2 = 0.f, a3 = 0.f;
    int e = 0;
    for (; e + 8 <= cnt; e += 8) {   // this slot handles 4 of the 8 edges
        uint4 q = idx4[e >> 3];
        int s0 = (q.x >> sh) & 0xFFFF;
        int s1 = (q.y >> sh) & 0xFFFF;
        int s2 = (q.z >> sh) & 0xFFFF;
        int s3 = (q.w >> sh) & 0xFFFF;
        uint2 u0 = f2[s0 * 16 + cl];
        uint2 u1 = f2[s1 * 16 + cl];
        uint2 u2 = f2[s2 * 16 + cl];
        uint2 u3 = f2[s3 * 16 + cl];
        // fp16 pairwise tree (2 roundings) then one fp32 accumulate
        __half2 lo = __hadd2(__hadd2(*(__half2*)&u0.x, *(__half2*)&u1.x),
                             __hadd2(*(__half2*)&u2.x, *(__half2*)&u3.x));
        __half2 hi = __hadd2(__hadd2(*(__half2*)&u0.y, *(__half2*)&u1.y),
                             __hadd2(*(__half2*)&u2.y, *(__half2*)&u3.y));
        float2 plo = __half22float2(lo);
        float2 phi = __half22float2(hi);
        a0 += plo.x; a1 += plo.y; a2 += phi.x; a3 += phi.y;
    }
    for (; e < cnt; e += 2) {      // tail: warp-uniform bound, per-slot guard
        if (e + eslot < cnt) {
            int s = row[e + eslot];
            uint2 u = f2[s * 16 + cl];
            float2 p;
            p = __half22float2(*(__half2*)&u.x); a0 += p.x; a1 += p.y;
            p = __half22float2(*(__half2*)&u.y); a2 += p.x; a3 += p.y;
        }
    }
    // combine the two edge-slot halves
    a0 += __shfl_xor_sync(~0u, a0, 16);
    a1 += __shfl_xor_sync(~0u, a1, 16);
    a2 += __shfl_xor_sync(~0u, a2, 16);
    a3 += __shfl_xor_sync(~0u, a3, 16);
    float4 b = ((const float4*)bias)[cl];
    a0 = fmaxf(a0 + b.x, 0.f);
    a1 = fmaxf(a1 + b.y, 0.f);
    a2 = fmaxf(a2 + b.z, 0.f);
    a3 = fmaxf(a3 + b.w, 0.f);
    if (!PROJ) {
        if (eslot == 0)
            ((float4*)out)[n * 16 + cl] = make_float4(a0, a1, a2, a3);
    } else {
        // project 64 -> 7 (bias b3 added post-aggregation in k_agg7)
        float pj[7];
        int k0 = cl * 4;
        #pragma unroll
        for (int j = 0; j < 7; j++) {
            const float* wj = &sW3T[j * 64 + k0];
            pj[j] = a0 * wj[0] + a1 * wj[1] + a2 * wj[2] + a3 * wj[3];
        }
        #pragma unroll
        for (int o = 8; o; o >>= 1)
            #pragma unroll
            for (int j = 0; j < 7; j++)
                pj[j] += __shfl_xor_sync(~0u, pj[j], o, 16);
        if (lane == 0) {
            __half2 h0 = __floats2half2_rn(pj[0], pj[1]);
            __half2 h1 = __floats2half2_rn(pj[2], pj[3]);
            __half2 h2v = __floats2half2_rn(pj[4], pj[5]);
            __half2 h3v = __floats2half2_rn(pj[6], 0.f);
            uint4 pk = {*(unsigned*)&h0, *(unsigned*)&h1,
                        *(unsigned*)&h2v, *(unsigned*)&h3v};
            *(uint4*)&g_h3h[n * 8] = pk;
        }
    }
}

// -------- aggregation 7ch (fp16 in) + bias + log_softmax, thread per node --------

__global__ __launch_bounds__(256) void k_agg7(const float* __restrict__ b3,
                                              float* __restrict__ out) {
    int n = blockIdx.x * blockDim.x + threadIdx.x;
    if (n >= N_NODES) return;
    int cnt = min(g_cnt[n], BKT);
    const unsigned short* __restrict__ row = g_bucket + n * BKT;
    const uint4* __restrict__ p = (const uint4*)g_h3h;
    float a[7] = {};
    int e = 0;
    for (; e + 2 <= cnt; e += 2) {
        int s0 = row[e], s1 = row[e + 1];
        uint4 q0 = p[s0];
        uint4 q1 = p[s1];
        __half2 h0 = __hadd2(*(__half2*)&q0.x, *(__half2*)&q1.x);
        __half2 h1 = __hadd2(*(__half2*)&q0.y, *(__half2*)&q1.y);
        __half2 h2v = __hadd2(*(__half2*)&q0.z, *(__half2*)&q1.z);
        __half2 h3v = __hadd2(*(__half2*)&q0.w, *(__half2*)&q1.w);
        float2 f0 = __half22float2(h0);
        float2 f1 = __half22float2(h1);
        float2 f2v = __half22float2(h2v);
        float2 f3 = __half22float2(h3v);
        a[0] += f0.x; a[1] += f0.y; a[2] += f1.x; a[3] += f1.y;
        a[4] += f2v.x; a[5] += f2v.y; a[6] += f3.x;
    }
    for (; e < cnt; e++) {
        uint4 q = p[row[e]];
        float2 f0 = __half22float2(*(__half2*)&q.x);
        float2 f1 = __half22float2(*(__half2*)&q.y);
        float2 f2v = __half22float2(*(__half2*)&q.z);
        float2 f3 = __half22float2(*(__half2*)&q.w);
        a[0] += f0.x; a[1] += f0.y; a[2] += f1.x; a[3] += f1.y;
        a[4] += f2v.x; a[5] += f2v.y; a[6] += f3.x;
    }
    #pragma unroll
    for (int j = 0; j < 7; j++) a[j] += b3[j];
    float m = a[0];
    #pragma unroll
    for (int j = 1; j < 7; j++) m = fmaxf(m, a[j]);
    float se = 0.f;
    #pragma unroll
    for (int j = 0; j < 7; j++) se += __expf(a[j] - m);
    float ls = __logf(se);
    #pragma unroll
    for (int j = 0; j < 7; j++) out[n * 7 + j] = a[j] - m - ls;
}

// ---------------- launch (R8 structure: side-stream scatter) ----------------

static cudaStream_t g_s2 = nullptr;
static cudaEvent_t g_evF = nullptr, g_evJ = nullptr;

extern "C" void kernel_launch(void* const* d_in, const int* in_sizes, int n_in,
                              void* d_out, int out_size) {
    const float* x = (const float*)d_in[0];
    const int* ei = (const int*)d_in[1];
    const float* W1 = (const float*)d_in[2];
    const float* b1 = (const float*)d_in[3];
    const float* W2 = (const float*)d_in[4];
    const float* b2 = (const float*)d_in[5];
    const float* W3 = (const float*)d_in[6];
    const float* b3 = (const float*)d_in[7];
    float* out = (float*)d_out;

    if (!g_s2) {
        cudaStreamCreateWithFlags(&g_s2, cudaStreamNonBlocking);
        cudaEventCreateWithFlags(&g_evF, cudaEventDisableTiming);
        cudaEventCreateWithFlags(&g_evJ, cudaEventDisableTiming);
    }

    void *pA, *pB, *pw1, *pw2;
    cudaGetSymbolAddress(&pA, g_hA);
    cudaGetSymbolAddress(&pB, g_bufB);
    cudaGetSymbolAddress(&pw1, g_wt1);
    cudaGetSymbolAddress(&pw2, g_wt2);

    // zero counters + weight transposes (one kernel, main stream)
    k_zero_prep<<<(N_NODES + 8704 + 255) / 256, 256>>>(W1, W2, W3);

    // fork: bucket scatter on side stream (needs zeroed counters)
    cudaEventRecord(g_evF, 0);
    cudaStreamWaitEvent(g_s2, g_evF, 0);
    k_scatter<<<(N_EDGES / 8 + 255) / 256, 256, 0, g_s2>>>(ei);
    cudaEventRecord(g_evJ, g_s2);

    // main stream: layer-1 GEMM (independent of buckets)
    k_gemm64h<<<(N_NODES + 63) / 64, 256>>>(x, (const float*)pw1, (__half*)pA);

    // join
    cudaStreamWaitEvent(0, g_evJ, 0);

    // layer 2
    k_agg64v<false><<<(N_NODES * 32 + 255) / 256, 256>>>((const uint2*)pA, b1, (float*)pB);
    k_gemm64h<<<(N_NODES + 63) / 64, 256>>>((const float*)pB, (const float*)pw2, (__half*)pA);
    // layer 3: agg + fused projection, then final agg + log_softmax
    k_agg64v<true><<<(N_NODES * 32 + 255) / 256, 256>>>((const uint2*)pA, b2, nullptr);
    k_agg7<<<(N_NODES + 255) / 256, 256>>>(b3, out);
}

// round 12
// speedup vs baseline: 1.1144x; 1.0035x over previous
#include <cuda_runtime.h>
#include <cuda_fp16.h>

#define N_NODES 50000
#define N_EDGES 1600000
#define BKT 128  // fixed bucket capacity per dst (deg ~ Poisson(32); P(>128) ~ 1e-40)

// ---- scratch (static __device__, no allocs) ----
// g_cnt: zeroed at module load; k_agg7 (last consumer) re-zeroes it each call,
// so every kernel_launch invocation (correctness run, each graph replay) sees
// zeroed counters without a dedicated zeroing kernel.
__device__ int g_cnt[N_NODES];
__device__ __align__(16) unsigned short g_bucket[N_NODES * BKT];
__device__ __half g_hA[N_NODES * 64];    // pre-agg features, fp16
__device__ float g_bufB[N_NODES * 64];   // post-agg features, fp32
__device__ __half g_h3h[N_NODES * 8];    // layer-3 pre-agg, fp16 (7 used + pad)
__device__ float g_wt1[64 * 64];
__device__ float g_wt2[64 * 64];
__device__ float g_wt3[64 * 8];          // [k*8+j]

// -------- weight transposes only (Wt[k][j] = W[j][k]) --------

__global__ void k_prep_w(const float* __restrict__ W1, const float* __restrict__ W2,
                         const float* __restrict__ W3) {
    int t = blockIdx.x * blockDim.x + threadIdx.x;
    if (t < 4096) {
        int j = t >> 6, k = t & 63;
        g_wt1[k * 64 + j] = W1[t];
        g_wt2[k * 64 + j] = W2[t];
    }
    if (t < 512) {
        int k = t >> 3, j = t & 7;
        g_wt3[t] = (j < 7) ? W3[j * 64 + k] : 0.f;
    }
}

// ------ direct bucket scatter: no hist, no scan; 8 edges/thread ------

__global__ void k_scatter(const int* __restrict__ ei) {
    int i = (blockIdx.x * blockDim.x + threadIdx.x) * 8;
    if (i < N_EDGES) {
        int4 sA = *(const int4*)&ei[i];
        int4 sB = *(const int4*)&ei[i + 4];
        int4 dA = *(const int4*)&ei[N_EDGES + i];
        int4 dB = *(const int4*)&ei[N_EDGES + i + 4];
        int p0 = ((unsigned)dA.x < N_NODES) ? atomicAdd(&g_cnt[dA.x], 1) : -1;
        int p1 = ((unsigned)dA.y < N_NODES) ? atomicAdd(&g_cnt[dA.y], 1) : -1;
        int p2 = ((unsigned)dA.z < N_NODES) ? atomicAdd(&g_cnt[dA.z], 1) : -1;
        int p3 = ((unsigned)dA.w < N_NODES) ? atomicAdd(&g_cnt[dA.w], 1) : -1;
        int p4 = ((unsigned)dB.x < N_NODES) ? atomicAdd(&g_cnt[dB.x], 1) : -1;
        int p5 = ((unsigned)dB.y < N_NODES) ? atomicAdd(&g_cnt[dB.y], 1) : -1;
        int p6 = ((unsigned)dB.z < N_NODES) ? atomicAdd(&g_cnt[dB.z], 1) : -1;
        int p7 = ((unsigned)dB.w < N_NODES) ? atomicAdd(&g_cnt[dB.w], 1) : -1;
        if ((unsigned)p0 < BKT) g_bucket[dA.x * BKT + p0] = (unsigned short)sA.x;
        if ((unsigned)p1 < BKT) g_bucket[dA.y * BKT + p1] = (unsigned short)sA.y;
        if ((unsigned)p2 < BKT) g_bucket[dA.z * BKT + p2] = (unsigned short)sA.z;
        if ((unsigned)p3 < BKT) g_bucket[dA.w * BKT + p3] = (unsigned short)sA.w;
        if ((unsigned)p4 < BKT) g_bucket[dB.x * BKT + p4] = (unsigned short)sB.x;
        if ((unsigned)p5 < BKT) g_bucket[dB.y * BKT + p5] = (unsigned short)sB.y;
        if ((unsigned)p6 < BKT) g_bucket[dB.z * BKT + p6] = (unsigned short)sB.z;
        if ((unsigned)p7 < BKT) g_bucket[dB.w * BKT + p7] = (unsigned short)sB.w;
    }
}

// ---- packed f32x2 helpers (Blackwell FFMA2) ----

__device__ __forceinline__ unsigned long long pack2(float lo, float hi) {
    unsigned long long p;
    asm("mov.b64 %0, {%1, %2};" : "=l"(p) : "f"(lo), "f"(hi));
    return p;
}
__device__ __forceinline__ void unpack2(unsigned long long p, float& lo, float& hi) {
    asm("mov.b64 {%0, %1}, %2;" : "=f"(lo), "=f"(hi) : "l"(p));
}
__device__ __forceinline__ void ffma2(unsigned long long& d, unsigned long long a,
                                      unsigned long long b) {
    asm("fma.rn.f32x2 %0, %1, %2, %0;" : "+l"(d) : "l"(a), "l"(b));
}

// ------- GEMM 64x64 fp32-in -> fp16 out, f32x2 packed FMA -------

__global__ __launch_bounds__(256) void k_gemm64h(const float* __restrict__ in,
                                                 const float* __restrict__ wt,
                                                 __half* __restrict__ out) {
    __shared__ __align__(16) float sW[64 * 64];
    __shared__ float sX[64 * 65];
    int n0 = blockIdx.x * 64;
    for (int i = threadIdx.x; i < 4096; i += 256) sW[i] = wt[i];
    for (int i = threadIdx.x; i < 4096; i += 256) {
        int n = i >> 6, k = i & 63;
        sX[n * 65 + k] = (n0 + n < N_NODES) ? in[(n0 + n) * 64 + k] : 0.f;
    }
    __syncthreads();
    int tx = threadIdx.x & 15, ty = threadIdx.x >> 4;
    unsigned long long accP[4][2] = {};
    #pragma unroll 8
    for (int k = 0; k < 64; k++) {
        double2 wd = *(const double2*)&sW[k * 64 + tx * 4];
        unsigned long long w01 = __double_as_longlong(wd.x);
        unsigned long long w23 = __double_as_longlong(wd.y);
        #pragma unroll
        for (int i = 0; i < 4; i++) {
            float xv = sX[(ty * 4 + i) * 65 + k];
            unsigned long long xp = pack2(xv, xv);
            ffma2(accP[i][0], xp, w01);
            ffma2(accP[i][1], xp, w23);
        }
    }
    #pragma unroll
    for (int i = 0; i < 4; i++) {
        int n = n0 + ty * 4 + i;
        if (n < N_NODES) {
            float a0, a1, a2, a3;
            unpack2(accP[i][0], a0, a1);
            unpack2(accP[i][1], a2, a3);
            __half2 h0 = __floats2half2_rn(a0, a1);
            __half2 h1 = __floats2half2_rn(a2, a3);
            uint2 pk = {*(unsigned*)&h0, *(unsigned*)&h1};
            *(uint2*)&out[n * 64 + tx * 4] = pk;
        }
    }
}

// ---- aggregation 64ch: warp/node, 16 lanes x 4ch, 2 edge slots ----
// Each slot loads its own uint2 of 4 consecutive u16 indices (fixed-shift
// extraction), HADD2 pairwise tree over its 4 edges, then fp32 accumulate.
// PROJ=false: +bias,relu -> fp32 out.  PROJ=true: +bias,relu -> @W3 -> fp16 g_h3h.

template <bool PROJ>
__global__ __launch_bounds__(256) void k_agg64v(const uint2* __restrict__ f2,
                                                const float* __restrict__ bias,
                                                float* __restrict__ out) {
    __shared__ float sW3T[512];  // transposed W3: [j*64 + k]
    if (PROJ) {
        for (int i = threadIdx.x; i < 512; i += 256) {
            int j = i >> 6, k = i & 63;
            sW3T[i] = g_wt3[k * 8 + j];
        }
        __syncthreads();
    }
    int n = (blockIdx.x * blockDim.x + threadIdx.x) >> 5;
    int lane = threadIdx.x & 31;
    if (n >= N_NODES) return;
    int cl = lane & 15;            // channel group: 4 ch = [cl*4, cl*4+4)
    int eslot = lane >> 4;         // which 4-edge group of each 8
    int cnt = min(g_cnt[n], BKT);
    const unsigned short* __restrict__ row = g_bucket + n * BKT;
    float a0 = 0.f, a1 = 0.f, a2 = 0.f, a3 = 0.f;
    int e = 0;
    for (; e + 8 <= cnt; e += 8) {   // this slot handles 4 of the 8 edges
        uint2 q = *(const uint2*)(row + e + (eslot << 2));
        int s0 = q.x & 0xFFFF, s1 = q.x >> 16;
        int s2 = q.y & 0xFFFF, s3 = q.y >> 16;
        uint2 u0 = f2[s0 * 16 + cl];
        uint2 u1 = f2[s1 * 16 + cl];
        uint2 u2 = f2[s2 * 16 + cl];
        uint2 u3 = f2[s3 * 16 + cl];
        // fp16 pairwise tree (2 roundings) then one fp32 accumulate
        __half2 lo = __hadd2(__hadd2(*(__half2*)&u0.x, *(__half2*)&u1.x),
                             __hadd2(*(__half2*)&u2.x, *(__half2*)&u3.x));
        __half2 hi = __hadd2(__hadd2(*(__half2*)&u0.y, *(__half2*)&u1.y),
                             __hadd2(*(__half2*)&u2.y, *(__half2*)&u3.y));
        float2 plo = __half22float2(lo);
        float2 phi = __half22float2(hi);
        a0 += plo.x; a1 += plo.y; a2 += phi.x; a3 += phi.y;
    }
    for (; e < cnt; e += 2) {      // tail: warp-uniform bound, per-slot guard
        if (e + eslot < cnt) {
            int s = row[e + eslot];
            uint2 u = f2[s * 16 + cl];
            float2 p;
            p = __half22float2(*(__half2*)&u.x); a0 += p.x; a1 += p.y;
            p = __half22float2(*(__half2*)&u.y); a2 += p.x; a3 += p.y;
        }
    }
    // combine the two edge-slot halves
    a0 += __shfl_xor_sync(~0u, a0, 16);
    a1 += __shfl_xor_sync(~0u, a1, 16);
    a2 += __shfl_xor_sync(~0u, a2, 16);
    a3 += __shfl_xor_sync(~0u, a3, 16);
    float4 b = ((const float4*)bias)[cl];
    a0 = fmaxf(a0 + b.x, 0.f);
    a1 = fmaxf(a1 + b.y, 0.f);
    a2 = fmaxf(a2 + b.z, 0.f);
    a3 = fmaxf(a3 + b.w, 0.f);
    if (!PROJ) {
        if (eslot == 0)
            ((float4*)out)[n * 16 + cl] = make_float4(a0, a1, a2, a3);
    } else {
        // project 64 -> 7 (bias b3 added post-aggregation in k_agg7)
        float pj[7];
        int k0 = cl * 4;
        #pragma unroll
        for (int j = 0; j < 7; j++) {
            const float* wj = &sW3T[j * 64 + k0];
            pj[j] = a0 * wj[0] + a1 * wj[1] + a2 * wj[2] + a3 * wj[3];
        }
        #pragma unroll
        for (int o = 8; o; o >>= 1)
            #pragma unroll
            for (int j = 0; j < 7; j++)
                pj[j] += __shfl_xor_sync(~0u, pj[j], o, 16);
        if (lane == 0) {
            __half2 h0 = __floats2half2_rn(pj[0], pj[1]);
            __half2 h1 = __floats2half2_rn(pj[2], pj[3]);
            __half2 h2v = __floats2half2_rn(pj[4], pj[5]);
            __half2 h3v = __floats2half2_rn(pj[6], 0.f);
            uint4 pk = {*(unsigned*)&h0, *(unsigned*)&h1,
                        *(unsigned*)&h2v, *(unsigned*)&h3v};
            *(uint4*)&g_h3h[n * 8] = pk;
        }
    }
}

// ---- aggregation 7ch + bias + log_softmax, thread per node; zeroes g_cnt ----

__global__ __launch_bounds__(256) void k_agg7(const float* __restrict__ b3,
                                              float* __restrict__ out) {
    int n = blockIdx.x * blockDim.x + threadIdx.x;
    if (n >= N_NODES) return;
    int cnt = min(g_cnt[n], BKT);
    g_cnt[n] = 0;  // self-clean: next kernel_launch call sees zeroed counters
    const unsigned short* __restrict__ row = g_bucket + n * BKT;
    const uint4* __restrict__ p = (const uint4*)g_h3h;
    float a[7] = {};
    int e = 0;
    for (; e + 2 <= cnt; e += 2) {
        int s0 = row[e], s1 = row[e + 1];
        uint4 q0 = p[s0];
        uint4 q1 = p[s1];
        __half2 h0 = __hadd2(*(__half2*)&q0.x, *(__half2*)&q1.x);
        __half2 h1 = __hadd2(*(__half2*)&q0.y, *(__half2*)&q1.y);
        __half2 h2v = __hadd2(*(__half2*)&q0.z, *(__half2*)&q1.z);
        __half2 h3v = __hadd2(*(__half2*)&q0.w, *(__half2*)&q1.w);
        float2 f0 = __half22float2(h0);
        float2 f1 = __half22float2(h1);
        float2 f2v = __half22float2(h2v);
        float2 f3 = __half22float2(h3v);
        a[0] += f0.x; a[1] += f0.y; a[2] += f1.x; a[3] += f1.y;
        a[4] += f2v.x; a[5] += f2v.y; a[6] += f3.x;
    }
    for (; e < cnt; e++) {
        uint4 q = p[row[e]];
        float2 f0 = __half22float2(*(__half2*)&q.x);
        float2 f1 = __half22float2(*(__half2*)&q.y);
        float2 f2v = __half22float2(*(__half2*)&q.z);
        float2 f3 = __half22float2(*(__half2*)&q.w);
        a[0] += f0.x; a[1] += f0.y; a[2] += f1.x; a[3] += f1.y;
        a[4] += f2v.x; a[5] += f2v.y; a[6] += f3.x;
    }
    #pragma unroll
    for (int j = 0; j < 7; j++) a[j] += b3[j];
    float m = a[0];
    #pragma unroll
    for (int j = 1; j < 7; j++) m = fmaxf(m, a[j]);
    float se = 0.f;
    #pragma unroll
    for (int j = 0; j < 7; j++) se += __expf(a[j] - m);
    float ls = __logf(se);
    #pragma unroll
    for (int j = 0; j < 7; j++) out[n * 7 + j] = a[j] - m - ls;
}

// ---- launch: scatter at t=0 on SIDE stream; compute chain stays on stream 0 ----

static cudaStream_t g_s2 = nullptr;
static cudaEvent_t g_evF = nullptr, g_evJ = nullptr;

extern "C" void kernel_launch(void* const* d_in, const int* in_sizes, int n_in,
                              void* d_out, int out_size) {
    const float* x = (const float*)d_in[0];
    const int* ei = (const int*)d_in[1];
    const float* W1 = (const float*)d_in[2];
    const float* b1 = (const float*)d_in[3];
    const float* W2 = (const float*)d_in[4];
    const float* b2 = (const float*)d_in[5];
    const float* W3 = (const float*)d_in[6];
    const float* b3 = (const float*)d_in[7];
    float* out = (float*)d_out;

    if (!g_s2) {
        cudaStreamCreateWithFlags(&g_s2, cudaStreamNonBlocking);
        cudaEventCreateWithFlags(&g_evF, cudaEventDisableTiming);
        cudaEventCreateWithFlags(&g_evJ, cudaEventDisableTiming);
    }

    void *pA, *pB, *pw1, *pw2;
    cudaGetSymbolAddress(&pA, g_hA);
    cudaGetSymbolAddress(&pB, g_bufB);
    cudaGetSymbolAddress(&pw1, g_wt1);
    cudaGetSymbolAddress(&pw2, g_wt2);

    // fork: bucket scatter starts immediately on side stream (g_cnt pre-zeroed)
    cudaEventRecord(g_evF, 0);
    cudaStreamWaitEvent(g_s2, g_evF, 0);
    k_scatter<<<(N_EDGES / 8 + 255) / 256, 256, 0, g_s2>>>(ei);
    cudaEventRecord(g_evJ, g_s2);

    // main stream: weight prep + layer-1 GEMM (independent of buckets)
    k_prep_w<<<18, 256>>>(W1, W2, W3);
    k_gemm64h<<<(N_NODES + 63) / 64, 256>>>(x, (const float*)pw1, (__half*)pA);

    // join
    cudaStreamWaitEvent(0, g_evJ, 0);

    // layer 2
    k_agg64v<false><<<(N_NODES * 32 + 255) / 256, 256>>>((const uint2*)pA, b1, (float*)pB);
    k_gemm64h<<<(N_NODES + 63) / 64, 256>>>((const float*)pB, (const float*)pw2, (__half*)pA);
    // layer 3: agg + fused projection, then final agg + log_softmax (+cnt reset)
    k_agg64v<true><<<(N_NODES * 32 + 255) / 256, 256>>>((const uint2*)pA, b2, nullptr);
    k_agg7<<<(N_NODES + 255) / 256, 256>>>(b3, out);
}

// round 13
// speedup vs baseline: 1.1373x; 1.0206x over previous
#include <cuda_runtime.h>
#include <cuda_fp16.h>

#define N_NODES 50000
#define N_EDGES 1600000
#define BKT 128  // fixed bucket capacity per dst (deg ~ Poisson(32); P(>128) ~ 1e-40)

// ---- scratch (static __device__, no allocs) ----
// g_cnt: zeroed at module load; k_agg7 (last consumer) re-zeroes it each call.
__device__ int g_cnt[N_NODES];
__device__ __align__(16) unsigned short g_bucket[N_NODES * BKT];
__device__ __half g_hA[N_NODES * 64];    // pre-agg features, fp16
__device__ __half g_hB[N_NODES * 64];    // post-agg layer-1 features, fp16
__device__ __half g_h3h[N_NODES * 8];    // layer-3 pre-agg, fp16 (7 used + pad)

// ------ direct bucket scatter: no hist, no scan; 8 edges/thread ------

__global__ void k_scatter(const int* __restrict__ ei) {
    int i = (blockIdx.x * blockDim.x + threadIdx.x) * 8;
    if (i < N_EDGES) {
        int4 sA = *(const int4*)&ei[i];
        int4 sB = *(const int4*)&ei[i + 4];
        int4 dA = *(const int4*)&ei[N_EDGES + i];
        int4 dB = *(const int4*)&ei[N_EDGES + i + 4];
        int p0 = ((unsigned)dA.x < N_NODES) ? atomicAdd(&g_cnt[dA.x], 1) : -1;
        int p1 = ((unsigned)dA.y < N_NODES) ? atomicAdd(&g_cnt[dA.y], 1) : -1;
        int p2 = ((unsigned)dA.z < N_NODES) ? atomicAdd(&g_cnt[dA.z], 1) : -1;
        int p3 = ((unsigned)dA.w < N_NODES) ? atomicAdd(&g_cnt[dA.w], 1) : -1;
        int p4 = ((unsigned)dB.x < N_NODES) ? atomicAdd(&g_cnt[dB.x], 1) : -1;
        int p5 = ((unsigned)dB.y < N_NODES) ? atomicAdd(&g_cnt[dB.y], 1) : -1;
        int p6 = ((unsigned)dB.z < N_NODES) ? atomicAdd(&g_cnt[dB.z], 1) : -1;
        int p7 = ((unsigned)dB.w < N_NODES) ? atomicAdd(&g_cnt[dB.w], 1) : -1;
        if ((unsigned)p0 < BKT) g_bucket[dA.x * BKT + p0] = (unsigned short)sA.x;
        if ((unsigned)p1 < BKT) g_bucket[dA.y * BKT + p1] = (unsigned short)sA.y;
        if ((unsigned)p2 < BKT) g_bucket[dA.z * BKT + p2] = (unsigned short)sA.z;
        if ((unsigned)p3 < BKT) g_bucket[dA.w * BKT + p3] = (unsigned short)sA.w;
        if ((unsigned)p4 < BKT) g_bucket[dB.x * BKT + p4] = (unsigned short)sB.x;
        if ((unsigned)p5 < BKT) g_bucket[dB.y * BKT + p5] = (unsigned short)sB.y;
        if ((unsigned)p6 < BKT) g_bucket[dB.z * BKT + p6] = (unsigned short)sB.z;
        if ((unsigned)p7 < BKT) g_bucket[dB.w * BKT + p7] = (unsigned short)sB.w;
    }
}

// ---- packed f32x2 helpers (Blackwell FFMA2) ----

__device__ __forceinline__ unsigned long long pack2(float lo, float hi) {
    unsigned long long p;
    asm("mov.b64 %0, {%1, %2};" : "=l"(p) : "f"(lo), "f"(hi));
    return p;
}
__device__ __forceinline__ void unpack2(unsigned long long p, float& lo, float& hi) {
    asm("mov.b64 {%0, %1}, %2;" : "=f"(lo), "=f"(hi) : "l"(p));
}
__device__ __forceinline__ void ffma2(unsigned long long& d, unsigned long long a,
                                      unsigned long long b) {
    asm("fma.rn.f32x2 %0, %1, %2, %0;" : "+l"(d) : "l"(a), "l"(b));
}

// ------- GEMM 64x64 -> fp16 out, in-kernel W transpose, f32x2 packed FMA -------
// HALF_IN: input features fp16 (layer 2) vs fp32 (layer 1).
// W is raw row-major [j][k]; transposed to sW[k*64+j] via sX staging.

template <bool HALF_IN>
__global__ __launch_bounds__(256) void k_gemm64(const void* __restrict__ in,
                                                const float* __restrict__ W,
                                                __half* __restrict__ out) {
    __shared__ __align__(16) float sW[64 * 64];
    __shared__ float sX[64 * 65];
    int n0 = blockIdx.x * 64;
    // phase 1: coalesced W load into sX staging (row j at stride 65)
    for (int i = threadIdx.x; i < 4096; i += 256) {
        sX[(i >> 6) * 65 + (i & 63)] = W[i];
    }
    __syncthreads();
    // phase 2: conflict-free transposed copy into sW[k*64+j]
    for (int i = threadIdx.x; i < 4096; i += 256) {
        int k = i >> 6, j = i & 63;
        sW[k * 64 + j] = sX[j * 65 + k];
    }
    __syncthreads();
    // phase 3: load X tile
    if (HALF_IN) {
        const __half* hin = (const __half*)in;
        for (int i = threadIdx.x; i < 2048; i += 256) {   // 2 halves per slot
            int n = i >> 5, k2 = i & 31;
            float2 v = make_float2(0.f, 0.f);
            if (n0 + n < N_NODES)
                v = __half22float2(*(const __half2*)&hin[(n0 + n) * 64 + k2 * 2]);
            sX[n * 65 + k2 * 2] = v.x;
            sX[n * 65 + k2 * 2 + 1] = v.y;
        }
    } else {
        const float* fin = (const float*)in;
        for (int i = threadIdx.x; i < 4096; i += 256) {
            int n = i >> 6, k = i & 63;
            sX[n * 65 + k] = (n0 + n < N_NODES) ? fin[(n0 + n) * 64 + k] : 0.f;
        }
    }
    __syncthreads();
    int tx = threadIdx.x & 15, ty = threadIdx.x >> 4;
    unsigned long long accP[4][2] = {};
    #pragma unroll 8
    for (int k = 0; k < 64; k++) {
        double2 wd = *(const double2*)&sW[k * 64 + tx * 4];
        unsigned long long w01 = __double_as_longlong(wd.x);
        unsigned long long w23 = __double_as_longlong(wd.y);
        #pragma unroll
        for (int i = 0; i < 4; i++) {
            float xv = sX[(ty * 4 + i) * 65 + k];
            unsigned long long xp = pack2(xv, xv);
            ffma2(accP[i][0], xp, w01);
            ffma2(accP[i][1], xp, w23);
        }
    }
    #pragma unroll
    for (int i = 0; i < 4; i++) {
        int n = n0 + ty * 4 + i;
        if (n < N_NODES) {
            float a0, a1, a2, a3;
            unpack2(accP[i][0], a0, a1);
            unpack2(accP[i][1], a2, a3);
            __half2 h0 = __floats2half2_rn(a0, a1);
            __half2 h1 = __floats2half2_rn(a2, a3);
            uint2 pk = {*(unsigned*)&h0, *(unsigned*)&h1};
            *(uint2*)&out[n * 64 + tx * 4] = pk;
        }
    }
}

// ---- aggregation 64ch: warp/node, 16 lanes x 4ch, 2 edge slots ----
// Per-slot uint2 index load (4 consecutive u16), HADD2 pairwise tree, fp32 accum.
// PROJ=false: +bias,relu -> fp16 out.  PROJ=true: +bias,relu -> @W3 -> fp16 g_h3h.

template <bool PROJ>
__global__ __launch_bounds__(256) void k_agg64v(const uint2* __restrict__ f2,
                                                const float* __restrict__ bias,
                                                const float* __restrict__ w3,
                                                __half* __restrict__ out) {
    __shared__ float sW3T[512];  // W3 row-major [j*64+k] == desired layout
    if (PROJ) {
        for (int i = threadIdx.x; i < 512; i += 256)
            sW3T[i] = (i < 448) ? w3[i] : 0.f;
        __syncthreads();
    }
    int n = (blockIdx.x * blockDim.x + threadIdx.x) >> 5;
    int lane = threadIdx.x & 31;
    if (n >= N_NODES) return;
    int cl = lane & 15;            // channel group: 4 ch = [cl*4, cl*4+4)
    int eslot = lane >> 4;         // which 4-edge group of each 8
    int cnt = min(g_cnt[n], BKT);
    const unsigned short* __restrict__ row = g_bucket + n * BKT;
    float a0 = 0.f, a1 = 0.f, a2 = 0.f, a3 = 0.f;
    int e = 0;
    for (; e + 8 <= cnt; e += 8) {   // this slot handles 4 of the 8 edges
        uint2 q = *(const uint2*)(row + e + (eslot << 2));
        int s0 = q.x & 0xFFFF, s1 = q.x >> 16;
        int s2 = q.y & 0xFFFF, s3 = q.y >> 16;
        uint2 u0 = f2[s0 * 16 + cl];
        uint2 u1 = f2[s1 * 16 + cl];
        uint2 u2 = f2[s2 * 16 + cl];
        uint2 u3 = f2[s3 * 16 + cl];
        __half2 lo = __hadd2(__hadd2(*(__half2*)&u0.x, *(__half2*)&u1.x),
                             __hadd2(*(__half2*)&u2.x, *(__half2*)&u3.x));
        __half2 hi = __hadd2(__hadd2(*(__half2*)&u0.y, *(__half2*)&u1.y),
                             __hadd2(*(__half2*)&u2.y, *(__half2*)&u3.y));
        float2 plo = __half22float2(lo);
        float2 phi = __half22float2(hi);
        a0 += plo.x; a1 += plo.y; a2 += phi.x; a3 += phi.y;
    }
    for (; e < cnt; e += 2) {      // tail: warp-uniform bound, per-slot guard
        if (e + eslot < cnt) {
            int s = row[e + eslot];
            uint2 u = f2[s * 16 + cl];
            float2 p;
            p = __half22float2(*(__half2*)&u.x); a0 += p.x; a1 += p.y;
            p = __half22float2(*(__half2*)&u.y); a2 += p.x; a3 += p.y;
        }
    }
    // combine the two edge-slot halves
    a0 += __shfl_xor_sync(~0u, a0, 16);
    a1 += __shfl_xor_sync(~0u, a1, 16);
    a2 += __shfl_xor_sync(~0u, a2, 16);
    a3 += __shfl_xor_sync(~0u, a3, 16);
    float4 b = ((const float4*)bias)[cl];
    a0 = fmaxf(a0 + b.x, 0.f);
    a1 = fmaxf(a1 + b.y, 0.f);
    a2 = fmaxf(a2 + b.z, 0.f);
    a3 = fmaxf(a3 + b.w, 0.f);
    if (!PROJ) {
        if (eslot == 0) {
            __half2 h0 = __floats2half2_rn(a0, a1);
            __half2 h1 = __floats2half2_rn(a2, a3);
            uint2 pk = {*(unsigned*)&h0, *(unsigned*)&h1};
            ((uint2*)out)[n * 16 + cl] = pk;
        }
    } else {
        // project 64 -> 7 (bias b3 added post-aggregation in k_agg7)
        float pj[7];
        int k0 = cl * 4;
        #pragma unroll
        for (int j = 0; j < 7; j++) {
            const float* wj = &sW3T[j * 64 + k0];
            pj[j] = a0 * wj[0] + a1 * wj[1] + a2 * wj[2] + a3 * wj[3];
        }
        #pragma unroll
        for (int o = 8; o; o >>= 1)
            #pragma unroll
            for (int j = 0; j < 7; j++)
                pj[j] += __shfl_xor_sync(~0u, pj[j], o, 16);
        if (lane == 0) {
            __half2 h0 = __floats2half2_rn(pj[0], pj[1]);
            __half2 h1 = __floats2half2_rn(pj[2], pj[3]);
            __half2 h2v = __floats2half2_rn(pj[4], pj[5]);
            __half2 h3v = __floats2half2_rn(pj[6], 0.f);
            uint4 pk = {*(unsigned*)&h0, *(unsigned*)&h1,
                        *(unsigned*)&h2v, *(unsigned*)&h3v};
            *(uint4*)&g_h3h[n * 8] = pk;
        }
    }
}

// ---- aggregation 7ch + bias + log_softmax, thread per node; zeroes g_cnt ----

__global__ __launch_bounds__(256) void k_agg7(const float* __restrict__ b3,
                                              float* __restrict__ out) {
    int n = blockIdx.x * blockDim.x + threadIdx.x;
    if (n >= N_NODES) return;
    int cnt = min(g_cnt[n], BKT);
    g_cnt[n] = 0;  // self-clean: next kernel_launch call sees zeroed counters
    const unsigned short* __restrict__ row = g_bucket + n * BKT;
    const uint4* __restrict__ p = (const uint4*)g_h3h;
    float a[7] = {};
    int e = 0;
    for (; e + 2 <= cnt; e += 2) {
        int s0 = row[e], s1 = row[e + 1];
        uint4 q0 = p[s0];
        uint4 q1 = p[s1];
        __half2 h0 = __hadd2(*(__half2*)&q0.x, *(__half2*)&q1.x);
        __half2 h1 = __hadd2(*(__half2*)&q0.y, *(__half2*)&q1.y);
        __half2 h2v = __hadd2(*(__half2*)&q0.z, *(__half2*)&q1.z);
        __half2 h3v = __hadd2(*(__half2*)&q0.w, *(__half2*)&q1.w);
        float2 f0 = __half22float2(h0);
        float2 f1 = __half22float2(h1);
        float2 f2v = __half22float2(h2v);
        float2 f3 = __half22float2(h3v);
        a[0] += f0.x; a[1] += f0.y; a[2] += f1.x; a[3] += f1.y;
        a[4] += f2v.x; a[5] += f2v.y; a[6] += f3.x;
    }
    for (; e < cnt; e++) {
        uint4 q = p[row[e]];
        float2 f0 = __half22float2(*(__half2*)&q.x);
        float2 f1 = __half22float2(*(__half2*)&q.y);
        float2 f2v = __half22float2(*(__half2*)&q.z);
        float2 f3 = __half22float2(*(__half2*)&q.w);
        a[0] += f0.x; a[1] += f0.y; a[2] += f1.x; a[3] += f1.y;
        a[4] += f2v.x; a[5] += f2v.y; a[6] += f3.x;
    }
    #pragma unroll
    for (int j = 0; j < 7; j++) a[j] += b3[j];
    float m = a[0];
    #pragma unroll
    for (int j = 1; j < 7; j++) m = fmaxf(m, a[j]);
    float se = 0.f;
    #pragma unroll
    for (int j = 0; j < 7; j++) se += __expf(a[j] - m);
    float ls = __logf(se);
    #pragma unroll
    for (int j = 0; j < 7; j++) out[n * 7 + j] = a[j] - m - ls;
}

// ---- launch: scatter at t=0 on side stream; 6 kernel nodes total ----

static cudaStream_t g_s2 = nullptr;
static cudaEvent_t g_evF = nullptr, g_evJ = nullptr;

extern "C" void kernel_launch(void* const* d_in, const int* in_sizes, int n_in,
                              void* d_out, int out_size) {
    const float* x = (const float*)d_in[0];
    const int* ei = (const int*)d_in[1];
    const float* W1 = (const float*)d_in[2];
    const float* b1 = (const float*)d_in[3];
    const float* W2 = (const float*)d_in[4];
    const float* b2 = (const float*)d_in[5];
    const float* W3 = (const float*)d_in[6];
    const float* b3 = (const float*)d_in[7];
    float* out = (float*)d_out;

    if (!g_s2) {
        cudaStreamCreateWithFlags(&g_s2, cudaStreamNonBlocking);
        cudaEventCreateWithFlags(&g_evF, cudaEventDisableTiming);
        cudaEventCreateWithFlags(&g_evJ, cudaEventDisableTiming);
    }

    void *pA, *pB;
    cudaGetSymbolAddress(&pA, g_hA);
    cudaGetSymbolAddress(&pB, g_hB);

    // fork: bucket scatter starts immediately on side stream (g_cnt pre-zeroed)
    cudaEventRecord(g_evF, 0);
    cudaStreamWaitEvent(g_s2, g_evF, 0);
    k_scatter<<<(N_EDGES / 8 + 255) / 256, 256, 0, g_s2>>>(ei);
    cudaEventRecord(g_evJ, g_s2);

    // main stream: layer-1 GEMM (in-kernel W transpose; independent of buckets)
    k_gemm64<false><<<(N_NODES + 63) / 64, 256>>>(x, W1, (__half*)pA);

    // join
    cudaStreamWaitEvent(0, g_evJ, 0);

    // layer 2
    k_agg64v<false><<<(N_NODES * 32 + 255) / 256, 256>>>((const uint2*)pA, b1,
                                                         nullptr, (__half*)pB);
    k_gemm64<true><<<(N_NODES + 63) / 64, 256>>>(pB, W2, (__half*)pA);
    // layer 3: agg + fused projection, then final agg + log_softmax (+cnt reset)
    k_agg64v<true><<<(N_NODES * 32 + 255) / 256, 256>>>((const uint2*)pA, b2,
                                                        W3, nullptr);
    k_agg7<<<(N_NODES + 255) / 256, 256>>>(b3, out);
}

// round 14
// speedup vs baseline: 1.1449x; 1.0066x over previous
#include <cuda_runtime.h>
#include <cuda_fp16.h>

#define N_NODES 50000
#define N_EDGES 1600000
#define BKT 128  // fixed bucket capacity per dst (deg ~ Poisson(32); P(>128) ~ 1e-40)

// ---- scratch (static __device__, no allocs) ----
// g_cnt: zeroed at module load; k_agg7 (last consumer) re-zeroes it each call.
__device__ int g_cnt[N_NODES];
__device__ __align__(16) unsigned short g_bucket[N_NODES * BKT];
__device__ __half g_hA[N_NODES * 64];    // pre-agg features, fp16
__device__ __half g_hB[N_NODES * 64];    // post-agg layer-1 features, fp16
__device__ __half g_h3h[N_NODES * 8];    // layer-3 pre-agg, fp16 (7 used + pad)
__device__ float g_wt2[64 * 64];         // W2 transposed [k*64+j], written by k_scatter

// ------ direct bucket scatter + W2 transpose side job; 8 edges/thread ------

__global__ void k_scatter(const int* __restrict__ ei, const float* __restrict__ W2) {
    int t = blockIdx.x * blockDim.x + threadIdx.x;
    if (t < 4096) {  // side job: transpose W2 for the post-join gemm2
        int j = t >> 6, k = t & 63;
        g_wt2[k * 64 + j] = W2[t];
    }
    int i = t * 8;
    if (i < N_EDGES) {
        int4 sA = *(const int4*)&ei[i];
        int4 sB = *(const int4*)&ei[i + 4];
        int4 dA = *(const int4*)&ei[N_EDGES + i];
        int4 dB = *(const int4*)&ei[N_EDGES + i + 4];
        int p0 = ((unsigned)dA.x < N_NODES) ? atomicAdd(&g_cnt[dA.x], 1) : -1;
        int p1 = ((unsigned)dA.y < N_NODES) ? atomicAdd(&g_cnt[dA.y], 1) : -1;
        int p2 = ((unsigned)dA.z < N_NODES) ? atomicAdd(&g_cnt[dA.z], 1) : -1;
        int p3 = ((unsigned)dA.w < N_NODES) ? atomicAdd(&g_cnt[dA.w], 1) : -1;
        int p4 = ((unsigned)dB.x < N_NODES) ? atomicAdd(&g_cnt[dB.x], 1) : -1;
        int p5 = ((unsigned)dB.y < N_NODES) ? atomicAdd(&g_cnt[dB.y], 1) : -1;
        int p6 = ((unsigned)dB.z < N_NODES) ? atomicAdd(&g_cnt[dB.z], 1) : -1;
        int p7 = ((unsigned)dB.w < N_NODES) ? atomicAdd(&g_cnt[dB.w], 1) : -1;
        if ((unsigned)p0 < BKT) g_bucket[dA.x * BKT + p0] = (unsigned short)sA.x;
        if ((unsigned)p1 < BKT) g_bucket[dA.y * BKT + p1] = (unsigned short)sA.y;
        if ((unsigned)p2 < BKT) g_bucket[dA.z * BKT + p2] = (unsigned short)sA.z;
        if ((unsigned)p3 < BKT) g_bucket[dA.w * BKT + p3] = (unsigned short)sA.w;
        if ((unsigned)p4 < BKT) g_bucket[dB.x * BKT + p4] = (unsigned short)sB.x;
        if ((unsigned)p5 < BKT) g_bucket[dB.y * BKT + p5] = (unsigned short)sB.y;
        if ((unsigned)p6 < BKT) g_bucket[dB.z * BKT + p6] = (unsigned short)sB.z;
        if ((unsigned)p7 < BKT) g_bucket[dB.w * BKT + p7] = (unsigned short)sB.w;
    }
}

// ---- packed f32x2 helpers (Blackwell FFMA2) ----

__device__ __forceinline__ unsigned long long pack2(float lo, float hi) {
    unsigned long long p;
    asm("mov.b64 %0, {%1, %2};" : "=l"(p) : "f"(lo), "f"(hi));
    return p;
}
__device__ __forceinline__ void unpack2(unsigned long long p, float& lo, float& hi) {
    asm("mov.b64 {%0, %1}, %2;" : "=f"(lo), "=f"(hi) : "l"(p));
}
__device__ __forceinline__ void ffma2(unsigned long long& d, unsigned long long a,
                                      unsigned long long b) {
    asm("fma.rn.f32x2 %0, %1, %2, %0;" : "+l"(d) : "l"(a), "l"(b));
}

// ------- GEMM 64x64 -> fp16 out, f32x2 packed FMA -------
// HALF_IN: fp16 vs fp32 input features.
// TRANS_W: W is raw row-major [j][k], transpose in-kernel (layer 1, cost hidden
//          by fork overlap).  Otherwise W is pre-transposed [k*64+j] (g_wt2).

template <bool HALF_IN, bool TRANS_W>
__global__ __launch_bounds__(256) void k_gemm64(const void* __restrict__ in,
                                                const float* __restrict__ W,
                                                __half* __restrict__ out) {
    __shared__ __align__(16) float sW[64 * 64];
    __shared__ float sX[64 * 65];
    int n0 = blockIdx.x * 64;
    if (TRANS_W) {
        // stage raw W rows into sX (stride 65), then conflict-free transpose
        for (int i = threadIdx.x; i < 4096; i += 256)
            sX[(i >> 6) * 65 + (i & 63)] = W[i];
        __syncthreads();
        for (int i = threadIdx.x; i < 4096; i += 256) {
            int k = i >> 6, j = i & 63;
            sW[k * 64 + j] = sX[j * 65 + k];
        }
        __syncthreads();
    } else {
        for (int i = threadIdx.x; i < 4096; i += 256) sW[i] = W[i];
    }
    // load X tile
    if (HALF_IN) {
        const __half* hin = (const __half*)in;
        for (int i = threadIdx.x; i < 2048; i += 256) {
            int n = i >> 5, k2 = i & 31;
            float2 v = make_float2(0.f, 0.f);
            if (n0 + n < N_NODES)
                v = __half22float2(*(const __half2*)&hin[(n0 + n) * 64 + k2 * 2]);
            sX[n * 65 + k2 * 2] = v.x;
            sX[n * 65 + k2 * 2 + 1] = v.y;
        }
    } else {
        const float* fin = (const float*)in;
        for (int i = threadIdx.x; i < 4096; i += 256) {
            int n = i >> 6, k = i & 63;
            sX[n * 65 + k] = (n0 + n < N_NODES) ? fin[(n0 + n) * 64 + k] : 0.f;
        }
    }
    __syncthreads();
    int tx = threadIdx.x & 15, ty = threadIdx.x >> 4;
    unsigned long long accP[4][2] = {};
    #pragma unroll 8
    for (int k = 0; k < 64; k++) {
        double2 wd = *(const double2*)&sW[k * 64 + tx * 4];
        unsigned long long w01 = __double_as_longlong(wd.x);
        unsigned long long w23 = __double_as_longlong(wd.y);
        #pragma unroll
        for (int i = 0; i < 4; i++) {
            float xv = sX[(ty * 4 + i) * 65 + k];
            unsigned long long xp = pack2(xv, xv);
            ffma2(accP[i][0], xp, w01);
            ffma2(accP[i][1], xp, w23);
        }
    }
    #pragma unroll
    for (int i = 0; i < 4; i++) {
        int n = n0 + ty * 4 + i;
        if (n < N_NODES) {
            float a0, a1, a2, a3;
            unpack2(accP[i][0], a0, a1);
            unpack2(accP[i][1], a2, a3);
            __half2 h0 = __floats2half2_rn(a0, a1);
            __half2 h1 = __floats2half2_rn(a2, a3);
            uint2 pk = {*(unsigned*)&h0, *(unsigned*)&h1};
            *(uint2*)&out[n * 64 + tx * 4] = pk;
        }
    }
}

// ---- aggregation 64ch: warp/node, 16 lanes x 4ch, 2 edge slots ----
// Per-slot uint2 index load (4 consecutive u16), HADD2 pairwise tree, fp32 accum.
// PROJ=false: +bias,relu -> fp16 out.  PROJ=true: +bias,relu -> @W3 -> fp16 g_h3h.

template <bool PROJ>
__global__ __launch_bounds__(256) void k_agg64v(const uint2* __restrict__ f2,
                                                const float* __restrict__ bias,
                                                const float* __restrict__ w3,
                                                __half* __restrict__ out) {
    __shared__ float sW3T[512];  // W3 row-major [j*64+k] == desired layout
    if (PROJ) {
        for (int i = threadIdx.x; i < 512; i += 256)
            sW3T[i] = (i < 448) ? w3[i] : 0.f;
        __syncthreads();
    }
    int n = (blockIdx.x * blockDim.x + threadIdx.x) >> 5;
    int lane = threadIdx.x & 31;
    if (n >= N_NODES) return;
    int cl = lane & 15;            // channel group: 4 ch = [cl*4, cl*4+4)
    int eslot = lane >> 4;         // which 4-edge group of each 8
    int cnt = min(g_cnt[n], BKT);
    const unsigned short* __restrict__ row = g_bucket + n * BKT;
    float a0 = 0.f, a1 = 0.f, a2 = 0.f, a3 = 0.f;
    int e = 0;
    for (; e + 8 <= cnt; e += 8) {   // this slot handles 4 of the 8 edges
        uint2 q = *(const uint2*)(row + e + (eslot << 2));
        int s0 = q.x & 0xFFFF, s1 = q.x >> 16;
        int s2 = q.y & 0xFFFF, s3 = q.y >> 16;
        uint2 u0 = f2[s0 * 16 + cl];
        uint2 u1 = f2[s1 * 16 + cl];
        uint2 u2 = f2[s2 * 16 + cl];
        uint2 u3 = f2[s3 * 16 + cl];
        __half2 lo = __hadd2(__hadd2(*(__half2*)&u0.x, *(__half2*)&u1.x),
                             __hadd2(*(__half2*)&u2.x, *(__half2*)&u3.x));
        __half2 hi = __hadd2(__hadd2(*(__half2*)&u0.y, *(__half2*)&u1.y),
                             __hadd2(*(__half2*)&u2.y, *(__half2*)&u3.y));
        float2 plo = __half22float2(lo);
        float2 phi = __half22float2(hi);
        a0 += plo.x; a1 += plo.y; a2 += phi.x; a3 += phi.y;
    }
    for (; e < cnt; e += 2) {      // tail: warp-uniform bound, per-slot guard
        if (e + eslot < cnt) {
            int s = row[e + eslot];
            uint2 u = f2[s * 16 + cl];
            float2 p;
            p = __half22float2(*(__half2*)&u.x); a0 += p.x; a1 += p.y;
            p = __half22float2(*(__half2*)&u.y); a2 += p.x; a3 += p.y;
        }
    }
    // combine the two edge-slot halves
    a0 += __shfl_xor_sync(~0u, a0, 16);
    a1 += __shfl_xor_sync(~0u, a1, 16);
    a2 += __shfl_xor_sync(~0u, a2, 16);
    a3 += __shfl_xor_sync(~0u, a3, 16);
    float4 b = ((const float4*)bias)[cl];
    a0 = fmaxf(a0 + b.x, 0.f);
    a1 = fmaxf(a1 + b.y, 0.f);
    a2 = fmaxf(a2 + b.z, 0.f);
    a3 = fmaxf(a3 + b.w, 0.f);
    if (!PROJ) {
        if (eslot == 0) {
            __half2 h0 = __floats2half2_rn(a0, a1);
            __half2 h1 = __floats2half2_rn(a2, a3);
            uint2 pk = {*(unsigned*)&h0, *(unsigned*)&h1};
            ((uint2*)out)[n * 16 + cl] = pk;
        }
    } else {
        // project 64 -> 7 (bias b3 added post-aggregation in k_agg7)
        float pj[7];
        int k0 = cl * 4;
        #pragma unroll
        for (int j = 0; j < 7; j++) {
            const float* wj = &sW3T[j * 64 + k0];
            pj[j] = a0 * wj[0] + a1 * wj[1] + a2 * wj[2] + a3 * wj[3];
        }
        #pragma unroll
        for (int o = 8; o; o >>= 1)
            #pragma unroll
            for (int j = 0; j < 7; j++)
                pj[j] += __shfl_xor_sync(~0u, pj[j], o, 16);
        if (lane == 0) {
            __half2 h0 = __floats2half2_rn(pj[0], pj[1]);
            __half2 h1 = __floats2half2_rn(pj[2], pj[3]);
            __half2 h2v = __floats2half2_rn(pj[4], pj[5]);
            __half2 h3v = __floats2half2_rn(pj[6], 0.f);
            uint4 pk = {*(unsigned*)&h0, *(unsigned*)&h1,
                        *(unsigned*)&h2v, *(unsigned*)&h3v};
            *(uint4*)&g_h3h[n * 8] = pk;
        }
    }
}

// ---- aggregation 7ch + bias + log_softmax, thread per node; zeroes g_cnt ----

__global__ __launch_bounds__(256) void k_agg7(const float* __restrict__ b3,
                                              float* __restrict__ out) {
    int n = blockIdx.x * blockDim.x + threadIdx.x;
    if (n >= N_NODES) return;
    int cnt = min(g_cnt[n], BKT);
    g_cnt[n] = 0;  // self-clean: next kernel_launch call sees zeroed counters
    const unsigned short* __restrict__ row = g_bucket + n * BKT;
    const uint4* __restrict__ p = (const uint4*)g_h3h;
    float a[7] = {};
    int e = 0;
    for (; e + 2 <= cnt; e += 2) {
        int s0 = row[e], s1 = row[e + 1];
        uint4 q0 = p[s0];
        uint4 q1 = p[s1];
        __half2 h0 = __hadd2(*(__half2*)&q0.x, *(__half2*)&q1.x);
        __half2 h1 = __hadd2(*(__half2*)&q0.y, *(__half2*)&q1.y);
        __half2 h2v = __hadd2(*(__half2*)&q0.z, *(__half2*)&q1.z);
        __half2 h3v = __hadd2(*(__half2*)&q0.w, *(__half2*)&q1.w);
        float2 f0 = __half22float2(h0);
        float2 f1 = __half22float2(h1);
        float2 f2v = __half22float2(h2v);
        float2 f3 = __half22float2(h3v);
        a[0] += f0.x; a[1] += f0.y; a[2] += f1.x; a[3] += f1.y;
        a[4] += f2v.x; a[5] += f2v.y; a[6] += f3.x;
    }
    for (; e < cnt; e++) {
        uint4 q = p[row[e]];
        float2 f0 = __half22float2(*(__half2*)&q.x);
        float2 f1 = __half22float2(*(__half2*)&q.y);
        float2 f2v = __half22float2(*(__half2*)&q.z);
        float2 f3 = __half22float2(*(__half2*)&q.w);
        a[0] += f0.x; a[1] += f0.y; a[2] += f1.x; a[3] += f1.y;
        a[4] += f2v.x; a[5] += f2v.y; a[6] += f3.x;
    }
    #pragma unroll
    for (int j = 0; j < 7; j++) a[j] += b3[j];
    float m = a[0];
    #pragma unroll
    for (int j = 1; j < 7; j++) m = fmaxf(m, a[j]);
    float se = 0.f;
    #pragma unroll
    for (int j = 0; j < 7; j++) se += __expf(a[j] - m);
    float ls = __logf(se);
    #pragma unroll
    for (int j = 0; j < 7; j++) out[n * 7 + j] = a[j] - m - ls;
}

// ---- launch: scatter(+W2 transpose) on side stream; 6 kernel nodes ----

static cudaStream_t g_s2 = nullptr;
static cudaEvent_t g_evF = nullptr, g_evJ = nullptr;

extern "C" void kernel_launch(void* const* d_in, const int* in_sizes, int n_in,
                              void* d_out, int out_size) {
    const float* x = (const float*)d_in[0];
    const int* ei = (const int*)d_in[1];
    const float* W1 = (const float*)d_in[2];
    const float* b1 = (const float*)d_in[3];
    const float* W2 = (const float*)d_in[4];
    const float* b2 = (const float*)d_in[5];
    const float* W3 = (const float*)d_in[6];
    const float* b3 = (const float*)d_in[7];
    float* out = (float*)d_out;

    if (!g_s2) {
        cudaStreamCreateWithFlags(&g_s2, cudaStreamNonBlocking);
        cudaEventCreateWithFlags(&g_evF, cudaEventDisableTiming);
        cudaEventCreateWithFlags(&g_evJ, cudaEventDisableTiming);
    }

    void *pA, *pB, *pw2;
    cudaGetSymbolAddress(&pA, g_hA);
    cudaGetSymbolAddress(&pB, g_hB);
    cudaGetSymbolAddress(&pw2, g_wt2);

    // fork: bucket scatter (+W2 transpose side job) on side stream
    cudaEventRecord(g_evF, 0);
    cudaStreamWaitEvent(g_s2, g_evF, 0);
    k_scatter<<<(N_EDGES / 8 + 255) / 256, 256, 0, g_s2>>>(ei, W2);
    cudaEventRecord(g_evJ, g_s2);

    // main stream: layer-1 GEMM (in-kernel W1 transpose; cost hidden by fork)
    k_gemm64<false, true><<<(N_NODES + 63) / 64, 256>>>(x, W1, (__half*)pA);

    // join
    cudaStreamWaitEvent(0, g_evJ, 0);

    // layer 2 (gemm reads pre-transposed g_wt2 -> fast path)
    k_agg64v<false><<<(N_NODES * 32 + 255) / 256, 256>>>((const uint2*)pA, b1,
                                                         nullptr, (__half*)pB);
    k_gemm64<true, false><<<(N_NODES + 63) / 64, 256>>>(pB, (const float*)pw2,
                                                        (__half*)pA);
    // layer 3: agg + fused projection, then final agg + log_softmax (+cnt reset)
    k_agg64v<true><<<(N_NODES * 32 + 255) / 256, 256>>>((const uint2*)pA, b2,
                                                        W3, nullptr);
    k_agg7<<<(N_NODES + 255) / 256, 256>>>(b3, out);
}

// round 15
// speedup vs baseline: 1.2365x; 1.0800x over previous
#include <cuda_runtime.h>
#include <cuda_fp16.h>
#include <mma.h>
using namespace nvcuda;

#define N_NODES 50000
#define NPAD 50048   // 391 blocks * 128 nodes, no bounds checks in wmma gemm
#define N_EDGES 1600000
#define BKT 128  // fixed bucket capacity per dst (deg ~ Poisson(32); P(>128) ~ 1e-40)

// ---- scratch (static __device__, no allocs) ----
// g_cnt: zeroed at module load; k_agg7 (last consumer) re-zeroes it each call.
__device__ int g_cnt[N_NODES];
__device__ __align__(16) unsigned short g_bucket[N_NODES * BKT];
__device__ __align__(32) __half g_xh[NPAD * 64];   // x converted to fp16
__device__ __align__(32) __half g_hA[NPAD * 64];   // pre-agg features, fp16
__device__ __align__(32) __half g_hB[NPAD * 64];   // post-agg layer-1 features, fp16
__device__ __half g_h3h[N_NODES * 8];              // layer-3 pre-agg, fp16
__device__ __half g_w1h[64 * 64];                  // W1^T fp16 [k*64+j]
__device__ __half g_w2h[64 * 64];                  // W2^T fp16 [k*64+j]

// ------ conversion: x -> fp16, W1/W2 -> fp16 transposed ------

__global__ void k_cvt(const float* __restrict__ x, const float* __restrict__ W1,
                      const float* __restrict__ W2) {
    int t = blockIdx.x * blockDim.x + threadIdx.x;
    if (t < 4096) {  // Wt[k*64+j] = W[j*64+k]
        int k = t >> 6, j = t & 63;
        g_w1h[t] = __float2half(W1[j * 64 + k]);
        g_w2h[t] = __float2half(W2[j * 64 + k]);
    }
    int i = t * 4;
    if (i < N_NODES * 64) {
        float4 v = *(const float4*)&x[i];
        __half2 h0 = __floats2half2_rn(v.x, v.y);
        __half2 h1 = __floats2half2_rn(v.z, v.w);
        uint2 pk = {*(unsigned*)&h0, *(unsigned*)&h1};
        *(uint2*)&g_xh[i] = pk;
    }
}

// ------ direct bucket scatter: no hist, no scan; 8 edges/thread ------

__global__ void k_scatter(const int* __restrict__ ei) {
    int i = (blockIdx.x * blockDim.x + threadIdx.x) * 8;
    if (i < N_EDGES) {
        int4 sA = *(const int4*)&ei[i];
        int4 sB = *(const int4*)&ei[i + 4];
        int4 dA = *(const int4*)&ei[N_EDGES + i];
        int4 dB = *(const int4*)&ei[N_EDGES + i + 4];
        int p0 = ((unsigned)dA.x < N_NODES) ? atomicAdd(&g_cnt[dA.x], 1) : -1;
        int p1 = ((unsigned)dA.y < N_NODES) ? atomicAdd(&g_cnt[dA.y], 1) : -1;
        int p2 = ((unsigned)dA.z < N_NODES) ? atomicAdd(&g_cnt[dA.z], 1) : -1;
        int p3 = ((unsigned)dA.w < N_NODES) ? atomicAdd(&g_cnt[dA.w], 1) : -1;
        int p4 = ((unsigned)dB.x < N_NODES) ? atomicAdd(&g_cnt[dB.x], 1) : -1;
        int p5 = ((unsigned)dB.y < N_NODES) ? atomicAdd(&g_cnt[dB.y], 1) : -1;
        int p6 = ((unsigned)dB.z < N_NODES) ? atomicAdd(&g_cnt[dB.z], 1) : -1;
        int p7 = ((unsigned)dB.w < N_NODES) ? atomicAdd(&g_cnt[dB.w], 1) : -1;
        if ((unsigned)p0 < BKT) g_bucket[dA.x * BKT + p0] = (unsigned short)sA.x;
        if ((unsigned)p1 < BKT) g_bucket[dA.y * BKT + p1] = (unsigned short)sA.y;
        if ((unsigned)p2 < BKT) g_bucket[dA.z * BKT + p2] = (unsigned short)sA.z;
        if ((unsigned)p3 < BKT) g_bucket[dA.w * BKT + p3] = (unsigned short)sA.w;
        if ((unsigned)p4 < BKT) g_bucket[dB.x * BKT + p4] = (unsigned short)sB.x;
        if ((unsigned)p5 < BKT) g_bucket[dB.y * BKT + p5] = (unsigned short)sB.y;
        if ((unsigned)p6 < BKT) g_bucket[dB.z * BKT + p6] = (unsigned short)sB.z;
        if ((unsigned)p7 < BKT) g_bucket[dB.w * BKT + p7] = (unsigned short)sB.w;
    }
}

// ------- GEMM 64x64 via WMMA (HMMA tensor pipe) -------
// out[n][j] = sum_k X[n][k] * Wt[k][j], all fp16 in / fp32 accum / fp16 out.
// 256 threads = 8 warps; warp handles 16 nodes; block 128 nodes; grid NPAD/128.

__global__ __launch_bounds__(256) void k_gemm_wmma(const __half* __restrict__ X,
                                                   const __half* __restrict__ Wt,
                                                   __half* __restrict__ out) {
    __shared__ __align__(32) __half sW[64 * 72];      // padded ldm=72
    __shared__ __align__(32) float stage[8][256];
    for (int t = threadIdx.x; t < 4096; t += 256)
        sW[(t >> 6) * 72 + (t & 63)] = Wt[t];
    __syncthreads();
    int warp = threadIdx.x >> 5;
    int lane = threadIdx.x & 31;
    int n0 = blockIdx.x * 128 + warp * 16;
    wmma::fragment<wmma::accumulator, 16, 16, 16, float> acc[4];
    #pragma unroll
    for (int jt = 0; jt < 4; jt++) wmma::fill_fragment(acc[jt], 0.f);
    #pragma unroll
    for (int kt = 0; kt < 4; kt++) {
        wmma::fragment<wmma::matrix_a, 16, 16, 16, __half, wmma::row_major> a;
        wmma::load_matrix_sync(a, X + n0 * 64 + kt * 16, 64);
        #pragma unroll
        for (int jt = 0; jt < 4; jt++) {
            wmma::fragment<wmma::matrix_b, 16, 16, 16, __half, wmma::row_major> b;
            wmma::load_matrix_sync(b, sW + kt * 16 * 72 + jt * 16, 72);
            wmma::mma_sync(acc[jt], a, b, acc[jt]);
        }
    }
    // write out: stage each 16x16 fp32 tile, convert to fp16, uint4 stores
    int r = lane >> 1, c0 = (lane & 1) * 8;
    #pragma unroll
    for (int jt = 0; jt < 4; jt++) {
        wmma::store_matrix_sync(&stage[warp][0], acc[jt], 16, wmma::mem_row_major);
        __syncwarp();
        float4 v0 = *(float4*)&stage[warp][r * 16 + c0];
        float4 v1 = *(float4*)&stage[warp][r * 16 + c0 + 4];
        __half2 h0 = __floats2half2_rn(v0.x, v0.y);
        __half2 h1 = __floats2half2_rn(v0.z, v0.w);
        __half2 h2 = __floats2half2_rn(v1.x, v1.y);
        __half2 h3 = __floats2half2_rn(v1.z, v1.w);
        uint4 pk = {*(unsigned*)&h0, *(unsigned*)&h1, *(unsigned*)&h2, *(unsigned*)&h3};
        *(uint4*)&out[(n0 + r) * 64 + jt * 16 + c0] = pk;
        __syncwarp();
    }
}

// ---- aggregation 64ch: warp/node, 16 lanes x 4ch, 2 edge slots ----
// Per-slot uint2 index load (4 consecutive u16), HADD2 pairwise tree, fp32 accum.
// PROJ=false: +bias,relu -> fp16 out.  PROJ=true: +bias,relu -> @W3 -> fp16 g_h3h.

template <bool PROJ>
__global__ __launch_bounds__(256) void k_agg64v(const uint2* __restrict__ f2,
                                                const float* __restrict__ bias,
                                                const float* __restrict__ w3,
                                                __half* __restrict__ out) {
    __shared__ float sW3T[512];  // W3 row-major [j*64+k] == desired layout
    if (PROJ) {
        for (int i = threadIdx.x; i < 512; i += 256)
            sW3T[i] = (i < 448) ? w3[i] : 0.f;
        __syncthreads();
    }
    int n = (blockIdx.x * blockDim.x + threadIdx.x) >> 5;
    int lane = threadIdx.x & 31;
    if (n >= N_NODES) return;
    int cl = lane & 15;            // channel group: 4 ch = [cl*4, cl*4+4)
    int eslot = lane >> 4;         // which 4-edge group of each 8
    int cnt = min(g_cnt[n], BKT);
    const unsigned short* __restrict__ row = g_bucket + n * BKT;
    float a0 = 0.f, a1 = 0.f, a2 = 0.f, a3 = 0.f;
    int e = 0;
    for (; e + 8 <= cnt; e += 8) {   // this slot handles 4 of the 8 edges
        uint2 q = *(const uint2*)(row + e + (eslot << 2));
        int s0 = q.x & 0xFFFF, s1 = q.x >> 16;
        int s2 = q.y & 0xFFFF, s3 = q.y >> 16;
        uint2 u0 = f2[s0 * 16 + cl];
        uint2 u1 = f2[s1 * 16 + cl];
        uint2 u2 = f2[s2 * 16 + cl];
        uint2 u3 = f2[s3 * 16 + cl];
        __half2 lo = __hadd2(__hadd2(*(__half2*)&u0.x, *(__half2*)&u1.x),
                             __hadd2(*(__half2*)&u2.x, *(__half2*)&u3.x));
        __half2 hi = __hadd2(__hadd2(*(__half2*)&u0.y, *(__half2*)&u1.y),
                             __hadd2(*(__half2*)&u2.y, *(__half2*)&u3.y));
        float2 plo = __half22float2(lo);
        float2 phi = __half22float2(hi);
        a0 += plo.x; a1 += plo.y; a2 += phi.x; a3 += phi.y;
    }
    for (; e < cnt; e += 2) {      // tail: warp-uniform bound, per-slot guard
        if (e + eslot < cnt) {
            int s = row[e + eslot];
            uint2 u = f2[s * 16 + cl];
            float2 p;
            p = __half22float2(*(__half2*)&u.x); a0 += p.x; a1 += p.y;
            p = __half22float2(*(__half2*)&u.y); a2 += p.x; a3 += p.y;
        }
    }
    // combine the two edge-slot halves
    a0 += __shfl_xor_sync(~0u, a0, 16);
    a1 += __shfl_xor_sync(~0u, a1, 16);
    a2 += __shfl_xor_sync(~0u, a2, 16);
    a3 += __shfl_xor_sync(~0u, a3, 16);
    float4 b = ((const float4*)bias)[cl];
    a0 = fmaxf(a0 + b.x, 0.f);
    a1 = fmaxf(a1 + b.y, 0.f);
    a2 = fmaxf(a2 + b.z, 0.f);
    a3 = fmaxf(a3 + b.w, 0.f);
    if (!PROJ) {
        if (eslot == 0) {
            __half2 h0 = __floats2half2_rn(a0, a1);
            __half2 h1 = __floats2half2_rn(a2, a3);
            uint2 pk = {*(unsigned*)&h0, *(unsigned*)&h1};
            ((uint2*)out)[n * 16 + cl] = pk;
        }
    } else {
        // project 64 -> 7 (bias b3 added post-aggregation in k_agg7)
        float pj[7];
        int k0 = cl * 4;
        #pragma unroll
        for (int j = 0; j < 7; j++) {
            const float* wj = &sW3T[j * 64 + k0];
            pj[j] = a0 * wj[0] + a1 * wj[1] + a2 * wj[2] + a3 * wj[3];
        }
        #pragma unroll
        for (int o = 8; o; o >>= 1)
            #pragma unroll
            for (int j = 0; j < 7; j++)
                pj[j] += __shfl_xor_sync(~0u, pj[j], o, 16);
        if (lane == 0) {
            __half2 h0 = __floats2half2_rn(pj[0], pj[1]);
            __half2 h1 = __floats2half2_rn(pj[2], pj[3]);
            __half2 h2v = __floats2half2_rn(pj[4], pj[5]);
            __half2 h3v = __floats2half2_rn(pj[6], 0.f);
            uint4 pk = {*(unsigned*)&h0, *(unsigned*)&h1,
                        *(unsigned*)&h2v, *(unsigned*)&h3v};
            *(uint4*)&g_h3h[n * 8] = pk;
        }
    }
}

// ---- aggregation 7ch + bias + log_softmax, thread per node; zeroes g_cnt ----

__global__ __launch_bounds__(256) void k_agg7(const float* __restrict__ b3,
                                              float* __restrict__ out) {
    int n = blockIdx.x * blockDim.x + threadIdx.x;
    if (n >= N_NODES) return;
    int cnt = min(g_cnt[n], BKT);
    g_cnt[n] = 0;  // self-clean: next kernel_launch call sees zeroed counters
    const unsigned short* __restrict__ row = g_bucket + n * BKT;
    const uint4* __restrict__ p = (const uint4*)g_h3h;
    float a[7] = {};
    int e = 0;
    for (; e + 2 <= cnt; e += 2) {
        int s0 = row[e], s1 = row[e + 1];
        uint4 q0 = p[s0];
        uint4 q1 = p[s1];
        __half2 h0 = __hadd2(*(__half2*)&q0.x, *(__half2*)&q1.x);
        __half2 h1 = __hadd2(*(__half2*)&q0.y, *(__half2*)&q1.y);
        __half2 h2v = __hadd2(*(__half2*)&q0.z, *(__half2*)&q1.z);
        __half2 h3v = __hadd2(*(__half2*)&q0.w, *(__half2*)&q1.w);
        float2 f0 = __half22float2(h0);
        float2 f1 = __half22float2(h1);
        float2 f2v = __half22float2(h2v);
        float2 f3 = __half22float2(h3v);
        a[0] += f0.x; a[1] += f0.y; a[2] += f1.x; a[3] += f1.y;
        a[4] += f2v.x; a[5] += f2v.y; a[6] += f3.x;
    }
    for (; e < cnt; e++) {
        uint4 q = p[row[e]];
        float2 f0 = __half22float2(*(__half2*)&q.x);
        float2 f1 = __half22float2(*(__half2*)&q.y);
        float2 f2v = __half22float2(*(__half2*)&q.z);
        float2 f3 = __half22float2(*(__half2*)&q.w);
        a[0] += f0.x; a[1] += f0.y; a[2] += f1.x; a[3] += f1.y;
        a[4] += f2v.x; a[5] += f2v.y; a[6] += f3.x;
    }
    #pragma unroll
    for (int j = 0; j < 7; j++) a[j] += b3[j];
    float m = a[0];
    #pragma unroll
    for (int j = 1; j < 7; j++) m = fmaxf(m, a[j]);
    float se = 0.f;
    #pragma unroll
    for (int j = 0; j < 7; j++) se += __expf(a[j] - m);
    float ls = __logf(se);
    #pragma unroll
    for (int j = 0; j < 7; j++) out[n * 7 + j] = a[j] - m - ls;
}

// ---- launch: scatter on side stream; cvt + wmma gemms on main ----

static cudaStream_t g_s2 = nullptr;
static cudaEvent_t g_evF = nullptr, g_evJ = nullptr;

extern "C" void kernel_launch(void* const* d_in, const int* in_sizes, int n_in,
                              void* d_out, int out_size) {
    const float* x = (const float*)d_in[0];
    const int* ei = (const int*)d_in[1];
    const float* W1 = (const float*)d_in[2];
    const float* b1 = (const float*)d_in[3];
    const float* W2 = (const float*)d_in[4];
    const float* b2 = (const float*)d_in[5];
    const float* W3 = (const float*)d_in[6];
    const float* b3 = (const float*)d_in[7];
    float* out = (float*)d_out;

    if (!g_s2) {
        cudaStreamCreateWithFlags(&g_s2, cudaStreamNonBlocking);
        cudaEventCreateWithFlags(&g_evF, cudaEventDisableTiming);
        cudaEventCreateWithFlags(&g_evJ, cudaEventDisableTiming);
    }

    void *pXh, *pA, *pB, *pw1, *pw2;
    cudaGetSymbolAddress(&pXh, g_xh);
    cudaGetSymbolAddress(&pA, g_hA);
    cudaGetSymbolAddress(&pB, g_hB);
    cudaGetSymbolAddress(&pw1, g_w1h);
    cudaGetSymbolAddress(&pw2, g_w2h);

    // fork: bucket scatter on side stream (g_cnt pre-zeroed / self-cleaned)
    cudaEventRecord(g_evF, 0);
    cudaStreamWaitEvent(g_s2, g_evF, 0);
    k_scatter<<<(N_EDGES / 8 + 255) / 256, 256, 0, g_s2>>>(ei);
    cudaEventRecord(g_evJ, g_s2);

    // main stream: fp16 conversions + layer-1 tensor-core GEMM (hidden by scatter)
    k_cvt<<<(N_NODES * 64 / 4 + 255) / 256, 256>>>(x, W1, W2);
    k_gemm_wmma<<<NPAD / 128, 256>>>((const __half*)pXh, (const __half*)pw1,
                                     (__half*)pA);

    // join
    cudaStreamWaitEvent(0, g_evJ, 0);

    // layer 2
    k_agg64v<false><<<(N_NODES * 32 + 255) / 256, 256>>>((const uint2*)pA, b1,
                                                         nullptr, (__half*)pB);
    k_gemm_wmma<<<NPAD / 128, 256>>>((const __half*)pB, (const __half*)pw2,
                                     (__half*)pA);
    // layer 3: agg + fused projection, then final agg + log_softmax (+cnt reset)
    k_agg64v<true><<<(N_NODES * 32 + 255) / 256, 256>>>((const uint2*)pA, b2,
                                                        W3, nullptr);
    k_agg7<<<(N_NODES + 255) / 256, 256>>>(b3, out);
}